// round 11
// baseline (speedup 1.0000x reference)
#include <cuda_runtime.h>
#include <cuda_bf16.h>
#include <cstdint>

#define D 64
#define NMAX 100000

__device__ float g_H1[NMAX * D];
__device__ float g_AGG1[NMAX * D];
__device__ float g_H2[NMAX * D];

// flags[0]: edge_index is int64 (1) or int32 (0)
// flags[1]: mask elem kind: 0 = uint8, 1 = float32, 2 = int32
__device__ int g_flags[2];

// ---- bf16 helpers -----------------------------------------------------------
__device__ __forceinline__ uint32_t bfpack(__nv_bfloat16 lo, __nv_bfloat16 hi) {
    return (uint32_t)__bfloat16_as_ushort(lo) | ((uint32_t)__bfloat16_as_ushort(hi) << 16);
}
// split v into (h, l) bf16 with v ~ h + l
__device__ __forceinline__ void bfsplit(float v, __nv_bfloat16& h, __nv_bfloat16& l) {
    h = __float2bfloat16_rn(v);
    l = __float2bfloat16_rn(v - __bfloat162float(h));
}
__device__ __forceinline__ void mma_bf16(float* c, const uint32_t* a, const uint32_t* b) {
    asm volatile(
        "mma.sync.aligned.m16n8k16.row.col.f32.bf16.bf16.f32 "
        "{%0,%1,%2,%3}, {%4,%5,%6,%7}, {%8,%9}, {%0,%1,%2,%3};"
        : "+f"(c[0]), "+f"(c[1]), "+f"(c[2]), "+f"(c[3])
        : "r"(a[0]), "r"(a[1]), "r"(a[2]), "r"(a[3]), "r"(b[0]), "r"(b[1]));
}

// ---------------------------------------------------------------------------
// Dtype detection — warp-parallel.
// ---------------------------------------------------------------------------
__global__ void detect_kernel(const int* __restrict__ ei_words,
                              const unsigned int* __restrict__ mask_words) {
    int lane = threadIdx.x;
    int odd_nonzero = 0;
    #pragma unroll
    for (int i = 0; i < 8; i++)
        if (ei_words[2 * (lane + i * 32) + 1] != 0) odd_nonzero = 1;
    int is64 = !__any_sync(0xFFFFFFFFu, odd_nonzero);

    int saw_f32 = 0, saw_hi = 0;
    #pragma unroll
    for (int i = 0; i < 128; i++) {
        unsigned int w = mask_words[lane + i * 32];
        if (w == 0x3F800000u) saw_f32 = 1;
        if ((w & 0xFFFFFF00u) != 0) saw_hi = 1;
    }
    int any_f32 = __any_sync(0xFFFFFFFFu, saw_f32);
    int any_hi  = __any_sync(0xFFFFFFFFu, saw_hi);
    if (lane == 0) {
        g_flags[0] = is64;
        g_flags[1] = any_f32 ? 1 : (any_hi ? 0 : 2);
    }
}

// ---------------------------------------------------------------------------
// Init: AGG1 = 0, OUT = broadcast(b2)
// ---------------------------------------------------------------------------
__global__ void init_kernel(float* __restrict__ agg1, float* __restrict__ out,
                            const float* __restrict__ b2, int n4) {
    int i = blockIdx.x * blockDim.x + threadIdx.x;
    if (i >= n4) return;
    ((float4*)agg1)[i] = make_float4(0.f, 0.f, 0.f, 0.f);
    int c4 = i & 15;
    ((float4*)out)[i] = __ldg(&((const float4*)b2)[c4]);
}

// ---------------------------------------------------------------------------
// Fused GEMM, double-buffered, bf16 m16n8k16 3-pass split, fp32 acc.
//   C[n_rows,64] = f(A) @ W   with the dropout x2 folded into W (W staged as 2W)
//   MODE 0: f(a) = mask ? a : 0
//   MODE 1: f(a) = mask ? relu(a + bias[k]) : 0
// BM=128, BN=64, BK=16, 256 threads = 8 warps (warp w: rows w*16..+16).
// smem word layout (stride 40 words/row; word = [row*40 + k2*2 + {hi,lo}]):
//   As buf0 @0      (128*40 = 5120 w)    As buf1 @5120
//   Bs buf0 @10240  (64*40  = 2560 w)    Bs buf1 @12800
// ---------------------------------------------------------------------------
#define GEMM_SMEM (15360 * 4)

template <int K, int MODE>
__global__ __launch_bounds__(256) void gemm_bf16(
        const float* __restrict__ A,
        const void* __restrict__ mask,
        const float* __restrict__ W,
        const float* __restrict__ bias,
        float* __restrict__ C, int n_rows) {
    extern __shared__ uint32_t sm[];
    __shared__ float sb[64];

    const int tid = threadIdx.x;
    const int mkind = g_flags[1];
    if (MODE == 1) {
        if (tid < 64) sb[tid] = bias[tid];
        __syncthreads();
    }

    uint32_t* AsB[2] = { sm, sm + 5120 };
    uint32_t* BsB[2] = { sm + 10240, sm + 12800 };

    const int row0 = blockIdx.x * 128;
    const int warp = tid >> 5;
    const int lane = tid & 31;
    const int gid = lane >> 2;     // 0..7
    const int tig = lane & 3;      // 0..3
    const int m0 = warp * 16;

    // A staging: thread -> (row ar, k-half ah: 8 k = 2 float4)
    const int ar = tid >> 1;
    const int ahalf = tid & 1;
    const int agr = row0 + ar;
    // B staging: thread -> (k-pair k2w, 2 n columns nb, nb+1)
    const int k2w = tid >> 5;          // 0..7
    const int nb = (tid & 31) * 2;     // 0..62

    float4 ra[2];
    uint4  rm[2];
    float2 rb0, rb1;   // W rows 2*k2w and 2*k2w+1, cols nb..nb+1

    auto load_tile = [&](int k0) {
        #pragma unroll
        for (int q = 0; q < 2; q++) {
            int kl = ahalf * 8 + q * 4;
            ra[q] = make_float4(0.f, 0.f, 0.f, 0.f);
            rm[q] = make_uint4(0u, 0u, 0u, 0u);
            if (agr < n_rows) {
                long gi = (long)agr * K + k0 + kl;
                ra[q] = *(const float4*)&A[gi];
                if (mkind == 0) {
                    rm[q].x = *(const unsigned int*)((const unsigned char*)mask + gi);
                } else if (mkind == 1) {
                    float4 f = *(const float4*)((const float*)mask + gi);
                    rm[q] = make_uint4(__float_as_uint(f.x), __float_as_uint(f.y),
                                       __float_as_uint(f.z), __float_as_uint(f.w));
                } else {
                    rm[q] = *(const uint4*)((const int*)mask + gi);
                }
            }
        }
        rb0 = *(const float2*)&W[(long)(k0 + 2 * k2w) * 64 + nb];
        rb1 = *(const float2*)&W[(long)(k0 + 2 * k2w + 1) * 64 + nb];
    };

    auto store_tile = [&](int buf, int k0) {
        uint32_t* as = AsB[buf];
        uint32_t* bs = BsB[buf];
        #pragma unroll
        for (int q = 0; q < 2; q++) {
            int kl = ahalf * 8 + q * 4;
            float v[4] = {ra[q].x, ra[q].y, ra[q].z, ra[q].w};
            if (MODE == 1) {
                #pragma unroll
                for (int j = 0; j < 4; j++) v[j] = fmaxf(v[j] + sb[kl + j], 0.f);
            }
            if (mkind == 0) {
                unsigned int mw = rm[q].x;
                v[0] = (mw & 0x000000FFu) ? v[0] : 0.f;
                v[1] = (mw & 0x0000FF00u) ? v[1] : 0.f;
                v[2] = (mw & 0x00FF0000u) ? v[2] : 0.f;
                v[3] = (mw & 0xFF000000u) ? v[3] : 0.f;
            } else {
                v[0] = rm[q].x ? v[0] : 0.f;
                v[1] = rm[q].y ? v[1] : 0.f;
                v[2] = rm[q].z ? v[2] : 0.f;
                v[3] = rm[q].w ? v[3] : 0.f;
            }
            __nv_bfloat16 h0, l0, h1, l1, h2, l2, h3, l3;
            bfsplit(v[0], h0, l0); bfsplit(v[1], h1, l1);
            bfsplit(v[2], h2, l2); bfsplit(v[3], h3, l3);
            uint4 w = make_uint4(bfpack(h0, h1), bfpack(l0, l1),
                                 bfpack(h2, h3), bfpack(l2, l3));
            *(uint4*)&as[ar * 40 + kl] = w;
        }
        // B: fold dropout x2 into weights
        float p00 = rb0.x * 2.f, p10 = rb1.x * 2.f;   // n = nb  : k, k+1
        float p01 = rb0.y * 2.f, p11 = rb1.y * 2.f;   // n = nb+1
        __nv_bfloat16 h00, l00, h10, l10, h01, l01, h11, l11;
        bfsplit(p00, h00, l00); bfsplit(p10, h10, l10);
        bfsplit(p01, h01, l01); bfsplit(p11, h11, l11);
        *(uint2*)&bs[nb * 40 + k2w * 2]       = make_uint2(bfpack(h00, h10), bfpack(l00, l10));
        *(uint2*)&bs[(nb + 1) * 40 + k2w * 2] = make_uint2(bfpack(h01, h11), bfpack(l01, l11));
    };

    float acc[8][4] = {};
    const int NIT = K / 16;

    load_tile(0);
    store_tile(0, 0);
    __syncthreads();

    for (int it = 0; it < NIT; it++) {
        int cur = it & 1;
        if (it + 1 < NIT) load_tile((it + 1) * 16);

        const uint32_t* as = AsB[cur];
        const uint32_t* bs = BsB[cur];
        int r0 = (m0 + gid) * 40 + tig * 2;
        int r1 = (m0 + gid + 8) * 40 + tig * 2;
        uint2 a0 = *(const uint2*)&as[r0];
        uint2 a1 = *(const uint2*)&as[r1];
        uint2 a2 = *(const uint2*)&as[r0 + 8];
        uint2 a3 = *(const uint2*)&as[r1 + 8];
        uint32_t ah[4] = {a0.x, a1.x, a2.x, a3.x};
        uint32_t al[4] = {a0.y, a1.y, a2.y, a3.y};

        #pragma unroll
        for (int nt = 0; nt < 8; nt++) {
            const uint32_t* bp = &bs[(nt * 8 + gid) * 40 + tig * 2];
            uint2 b0 = *(const uint2*)bp;
            uint2 b1 = *(const uint2*)(bp + 8);
            uint32_t bh[2] = {b0.x, b1.x};
            uint32_t bl[2] = {b0.y, b1.y};
            mma_bf16(acc[nt], ah, bh);
            mma_bf16(acc[nt], al, bh);
            mma_bf16(acc[nt], ah, bl);
        }

        if (it + 1 < NIT) {
            store_tile(cur ^ 1, (it + 1) * 16);
            __syncthreads();
        }
    }

    int ra_ = row0 + m0 + gid;
    int rb_ = ra_ + 8;
    #pragma unroll
    for (int nt = 0; nt < 8; nt++) {
        int col = nt * 8 + 2 * tig;
        if (ra_ < n_rows)
            *(float2*)&C[(long)ra_ * 64 + col] = make_float2(acc[nt][0], acc[nt][1]);
        if (rb_ < n_rows)
            *(float2*)&C[(long)rb_ * 64 + col] = make_float2(acc[nt][2], acc[nt][3]);
    }
}

// ---------------------------------------------------------------------------
// Edge scatter: out[dst] += H[src] * w. 16 lanes/edge, float4 + red.v4.f32.
// ---------------------------------------------------------------------------
__global__ __launch_bounds__(256) void scatter_kernel(
        const float* __restrict__ H,
        const void* __restrict__ ei_raw,
        const float* __restrict__ ew,
        float* __restrict__ out, int n_edges) {
    int e = blockIdx.x * 16 + (threadIdx.x >> 4);
    if (e >= n_edges) return;
    int c = (threadIdx.x & 15) * 4;
    int s, d;
    if (g_flags[0]) {
        const long long* ei = (const long long*)ei_raw;
        s = (int)__ldg(&ei[e]);
        d = (int)__ldg(&ei[n_edges + e]);
    } else {
        const int* ei = (const int*)ei_raw;
        s = __ldg(&ei[e]);
        d = __ldg(&ei[n_edges + e]);
    }
    float w = __ldg(&ew[e]);
    float4 v = __ldg((const float4*)&H[(long)s * 64 + c]);
    float* o = out + (long)d * 64 + c;
    asm volatile("red.global.add.v4.f32 [%0], {%1, %2, %3, %4};"
                 :: "l"(o), "f"(v.x * w), "f"(v.y * w), "f"(v.z * w), "f"(v.w * w)
                 : "memory");
}

// ---------------------------------------------------------------------------
// inputs: x, edge_index(2xE), edge_weight, W1, b1, W2, b2, mask1, mask2
// ---------------------------------------------------------------------------
extern "C" void kernel_launch(void* const* d_in, const int* in_sizes, int n_in,
                              void* d_out, int out_size) {
    const float* x  = (const float*)d_in[0];
    const void* ei  = d_in[1];
    const float* ew = (const float*)d_in[2];
    const float* W1 = (const float*)d_in[3];
    const float* b1 = (const float*)d_in[4];
    const float* W2 = (const float*)d_in[5];
    const float* b2 = (const float*)d_in[6];
    const void* m1  = d_in[7];
    const void* m2  = d_in[8];
    float* out = (float*)d_out;

    int n_nodes = in_sizes[0] / 384;
    int n_edges = in_sizes[2];

    float *H1, *AGG1, *H2;
    cudaGetSymbolAddress((void**)&H1, g_H1);
    cudaGetSymbolAddress((void**)&AGG1, g_AGG1);
    cudaGetSymbolAddress((void**)&H2, g_H2);

    cudaFuncSetAttribute(gemm_bf16<384, 0>, cudaFuncAttributeMaxDynamicSharedMemorySize, GEMM_SMEM);
    cudaFuncSetAttribute(gemm_bf16<64, 1>,  cudaFuncAttributeMaxDynamicSharedMemorySize, GEMM_SMEM);

    detect_kernel<<<1, 32>>>((const int*)ei, (const unsigned int*)m1);

    int n4 = n_nodes * 16;
    init_kernel<<<(n4 + 255) / 256, 256>>>(AGG1, out, b2, n4);

    int gb = (n_nodes + 127) / 128;
    int sbk = (n_edges + 15) / 16;
    gemm_bf16<384, 0><<<gb, 256, GEMM_SMEM>>>(x, m1, W1, nullptr, H1, n_nodes);
    scatter_kernel<<<sbk, 256>>>(H1, ei, ew, AGG1, n_edges);
    gemm_bf16<64, 1><<<gb, 256, GEMM_SMEM>>>(AGG1, m2, W2, b1, H2, n_nodes);
    scatter_kernel<<<sbk, 256>>>(H2, ei, ew, out, n_edges);
}

// round 12
// speedup vs baseline: 1.2849x; 1.2849x over previous
#include <cuda_runtime.h>
#include <cstdint>

#define D 64
#define NMAX 100000
#define EMAX 1600000

__device__ float g_H1[NMAX * D];
__device__ float g_AGG1[NMAX * D];
__device__ float g_H2[NMAX * D];
__device__ int   g_deg[NMAX];
__device__ int   g_offs[NMAX + 1];
__device__ int   g_cursor[NMAX];
__device__ uint2 g_srcw[EMAX];
__device__ int   g_bsum[128];

// flags[0]: edge_index is int64 (1) or int32 (0)
// flags[1]: mask elem kind: 0 = uint8, 1 = float32, 2 = int32
__device__ int g_flags[2];

// ---- tf32 helpers -----------------------------------------------------------
__device__ __forceinline__ uint32_t f2tf32(float f) {
    uint32_t r;
    asm("cvt.rna.tf32.f32 %0, %1;" : "=r"(r) : "f"(f));
    return r;
}
__device__ __forceinline__ void mma_tf32(float* c, const uint32_t* a, const uint32_t* b) {
    asm volatile(
        "mma.sync.aligned.m16n8k8.row.col.f32.tf32.tf32.f32 "
        "{%0,%1,%2,%3}, {%4,%5,%6,%7}, {%8,%9}, {%0,%1,%2,%3};"
        : "+f"(c[0]), "+f"(c[1]), "+f"(c[2]), "+f"(c[3])
        : "r"(a[0]), "r"(a[1]), "r"(a[2]), "r"(a[3]), "r"(b[0]), "r"(b[1]));
}

// ---------------------------------------------------------------------------
// Dtype detection — warp-parallel.
// ---------------------------------------------------------------------------
__global__ void detect_kernel(const int* __restrict__ ei_words,
                              const unsigned int* __restrict__ mask_words) {
    int lane = threadIdx.x;
    int odd_nonzero = 0;
    #pragma unroll
    for (int i = 0; i < 8; i++)
        if (ei_words[2 * (lane + i * 32) + 1] != 0) odd_nonzero = 1;
    int is64 = !__any_sync(0xFFFFFFFFu, odd_nonzero);

    int saw_f32 = 0, saw_hi = 0;
    #pragma unroll
    for (int i = 0; i < 128; i++) {
        unsigned int w = mask_words[lane + i * 32];
        if (w == 0x3F800000u) saw_f32 = 1;
        if ((w & 0xFFFFFF00u) != 0) saw_hi = 1;
    }
    int any_f32 = __any_sync(0xFFFFFFFFu, saw_f32);
    int any_hi  = __any_sync(0xFFFFFFFFu, saw_hi);
    if (lane == 0) {
        g_flags[0] = is64;
        g_flags[1] = any_f32 ? 1 : (any_hi ? 0 : 2);
    }
}

// ---------------------------------------------------------------------------
// CSR build: zero -> hist -> scan(3) -> fill
// ---------------------------------------------------------------------------
__global__ void zero_deg(int n) {
    int i = blockIdx.x * blockDim.x + threadIdx.x;
    if (i < n) g_deg[i] = 0;
}

__global__ void hist_kernel(const void* __restrict__ ei_raw, int n_edges) {
    int e = blockIdx.x * blockDim.x + threadIdx.x;
    if (e >= n_edges) return;
    int d = g_flags[0] ? (int)((const long long*)ei_raw)[n_edges + e]
                       : ((const int*)ei_raw)[n_edges + e];
    atomicAdd(&g_deg[d], 1);
}

__global__ void scan1_kernel(int n) {
    __shared__ int sh[1024];
    int i = blockIdx.x * 1024 + threadIdx.x;
    int v = (i < n) ? g_deg[i] : 0;
    sh[threadIdx.x] = v;
    __syncthreads();
    #pragma unroll
    for (int off = 1; off < 1024; off <<= 1) {
        int t = (threadIdx.x >= off) ? sh[threadIdx.x - off] : 0;
        __syncthreads();
        sh[threadIdx.x] += t;
        __syncthreads();
    }
    if (i < n) g_offs[i] = sh[threadIdx.x] - v;   // exclusive within block
    if (threadIdx.x == 1023) g_bsum[blockIdx.x] = sh[1023];
}

__global__ void scan2_kernel(int nb, int n, int n_edges) {
    if (threadIdx.x == 0) {
        int run = 0;
        for (int b = 0; b < nb; b++) { int t = g_bsum[b]; g_bsum[b] = run; run += t; }
        g_offs[n] = n_edges;
    }
}

__global__ void scan3_kernel(int n) {
    int i = blockIdx.x * blockDim.x + threadIdx.x;
    if (i >= n) return;
    int o = g_offs[i] + g_bsum[i >> 10];
    g_offs[i] = o;
    g_cursor[i] = o;
}

__global__ void fill_kernel(const void* __restrict__ ei_raw,
                            const float* __restrict__ ew, int n_edges) {
    int e = blockIdx.x * blockDim.x + threadIdx.x;
    if (e >= n_edges) return;
    int s, d;
    if (g_flags[0]) {
        const long long* ei = (const long long*)ei_raw;
        s = (int)ei[e];
        d = (int)ei[n_edges + e];
    } else {
        const int* ei = (const int*)ei_raw;
        s = ei[e];
        d = ei[n_edges + e];
    }
    int p = atomicAdd(&g_cursor[d], 1);
    g_srcw[p] = make_uint2((unsigned)s, __float_as_uint(__ldg(&ew[e])));
}

// ---------------------------------------------------------------------------
// CSR aggregation: out[node] = sum_{e in in(node)} H[src(e)] * w(e) (+ bias)
// One warp per node, float2 per lane. Unroll 4 for MLP.
// ---------------------------------------------------------------------------
__global__ __launch_bounds__(256) void agg_kernel(
        const float* __restrict__ H,
        const float* __restrict__ bias,   // may be null
        float* __restrict__ out, int n_nodes) {
    int node = blockIdx.x * 8 + (threadIdx.x >> 5);
    if (node >= n_nodes) return;
    int lane = threadIdx.x & 31;
    int beg = g_offs[node], end = g_offs[node + 1];

    float ax = 0.f, ay = 0.f;
    int e = beg;
    for (; e + 4 <= end; e += 4) {
        uint2 s0 = g_srcw[e],     s1 = g_srcw[e + 1];
        uint2 s2 = g_srcw[e + 2], s3 = g_srcw[e + 3];
        float2 v0 = *(const float2*)&H[(long)s0.x * 64 + lane * 2];
        float2 v1 = *(const float2*)&H[(long)s1.x * 64 + lane * 2];
        float2 v2 = *(const float2*)&H[(long)s2.x * 64 + lane * 2];
        float2 v3 = *(const float2*)&H[(long)s3.x * 64 + lane * 2];
        float w0 = __uint_as_float(s0.y), w1 = __uint_as_float(s1.y);
        float w2 = __uint_as_float(s2.y), w3 = __uint_as_float(s3.y);
        ax = fmaf(v0.x, w0, ax); ay = fmaf(v0.y, w0, ay);
        ax = fmaf(v1.x, w1, ax); ay = fmaf(v1.y, w1, ay);
        ax = fmaf(v2.x, w2, ax); ay = fmaf(v2.y, w2, ay);
        ax = fmaf(v3.x, w3, ax); ay = fmaf(v3.y, w3, ay);
    }
    for (; e < end; e++) {
        uint2 s0 = g_srcw[e];
        float2 v0 = *(const float2*)&H[(long)s0.x * 64 + lane * 2];
        float w0 = __uint_as_float(s0.y);
        ax = fmaf(v0.x, w0, ax); ay = fmaf(v0.y, w0, ay);
    }
    if (bias) {
        ax += __ldg(&bias[lane * 2]);
        ay += __ldg(&bias[lane * 2 + 1]);
    }
    *(float2*)&out[(long)node * 64 + lane * 2] = make_float2(ax, ay);
}

// ---------------------------------------------------------------------------
// Fused GEMM, double-buffered, tf32 tensor-core 3-pass (R9, best measured)
//   MODE 0: f(a) = mask ? a*2 : 0
//   MODE 1: f(a) = mask ? relu(a + bias[k])*2 : 0
// BM=128, BN=64, BK=16, 256 threads = 8 warps.
// ---------------------------------------------------------------------------
template <int K, int MODE>
__global__ __launch_bounds__(256) void gemm_tc(
        const float* __restrict__ A,
        const void* __restrict__ mask,
        const float* __restrict__ W,
        const float* __restrict__ bias,
        float* __restrict__ C, int n_rows) {
    __shared__ float As[2][128][20];
    __shared__ float Bs[2][16][72];
    __shared__ float sb[64];

    const int tid = threadIdx.x;
    const int mkind = g_flags[1];
    if (MODE == 1) {
        if (tid < 64) sb[tid] = bias[tid];
        __syncthreads();
    }

    const int row0 = blockIdx.x * 128;
    const int warp = tid >> 5;
    const int lane = tid & 31;
    const int gid = lane >> 2;
    const int tig = lane & 3;
    const int m0 = warp * 16;

    int arow[2], aq[2];
    #pragma unroll
    for (int i = 0; i < 2; i++) {
        int lin = tid + i * 256;
        arow[i] = lin >> 2;
        aq[i]   = lin & 3;
    }
    const int bkk = tid >> 4;
    const int bn4 = tid & 15;

    float4 ra[2];
    uint4  rm[2];
    float4 rb;

    auto load_tile = [&](int k0) {
        #pragma unroll
        for (int i = 0; i < 2; i++) {
            int gr = row0 + arow[i];
            ra[i] = make_float4(0.f, 0.f, 0.f, 0.f);
            rm[i] = make_uint4(0u, 0u, 0u, 0u);
            if (gr < n_rows) {
                long gi = (long)gr * K + k0 + aq[i] * 4;
                ra[i] = *(const float4*)&A[gi];
                if (mkind == 0) {
                    rm[i].x = *(const unsigned int*)((const unsigned char*)mask + gi);
                } else if (mkind == 1) {
                    float4 f = *(const float4*)((const float*)mask + gi);
                    rm[i] = make_uint4(__float_as_uint(f.x), __float_as_uint(f.y),
                                       __float_as_uint(f.z), __float_as_uint(f.w));
                } else {
                    rm[i] = *(const uint4*)((const int*)mask + gi);
                }
            }
        }
        rb = *(const float4*)&W[(long)(k0 + bkk) * 64 + bn4 * 4];
    };

    auto store_tile = [&](int buf, int k0) {
        #pragma unroll
        for (int i = 0; i < 2; i++) {
            float4 v = ra[i];
            float mv[4];
            if (mkind == 0) {
                unsigned int mw = rm[i].x;
                mv[0] = (mw & 0x000000FFu) ? 2.f : 0.f;
                mv[1] = (mw & 0x0000FF00u) ? 2.f : 0.f;
                mv[2] = (mw & 0x00FF0000u) ? 2.f : 0.f;
                mv[3] = (mw & 0xFF000000u) ? 2.f : 0.f;
            } else {
                mv[0] = rm[i].x ? 2.f : 0.f;
                mv[1] = rm[i].y ? 2.f : 0.f;
                mv[2] = rm[i].z ? 2.f : 0.f;
                mv[3] = rm[i].w ? 2.f : 0.f;
            }
            if (MODE == 1) {
                int kb = k0 + aq[i] * 4;
                v.x = fmaxf(v.x + sb[kb + 0], 0.f);
                v.y = fmaxf(v.y + sb[kb + 1], 0.f);
                v.z = fmaxf(v.z + sb[kb + 2], 0.f);
                v.w = fmaxf(v.w + sb[kb + 3], 0.f);
            }
            float4 o = make_float4(v.x * mv[0], v.y * mv[1], v.z * mv[2], v.w * mv[3]);
            *(float4*)&As[buf][arow[i]][aq[i] * 4] = o;
        }
        *(float4*)&Bs[buf][bkk][bn4 * 4] = rb;
    };

    float acc[8][4] = {};
    const int NIT = K / 16;

    load_tile(0);
    store_tile(0, 0);
    __syncthreads();

    for (int it = 0; it < NIT; it++) {
        int cur = it & 1;
        if (it + 1 < NIT) load_tile((it + 1) * 16);

        #pragma unroll
        for (int ks = 0; ks < 2; ks++) {
            int kk = ks * 8;
            float f0 = As[cur][m0 + gid    ][kk + tig];
            float f1 = As[cur][m0 + gid + 8][kk + tig];
            float f2 = As[cur][m0 + gid    ][kk + tig + 4];
            float f3 = As[cur][m0 + gid + 8][kk + tig + 4];
            uint32_t ah[4], al[4];
            ah[0] = f2tf32(f0); al[0] = f2tf32(f0 - __uint_as_float(ah[0]));
            ah[1] = f2tf32(f1); al[1] = f2tf32(f1 - __uint_as_float(ah[1]));
            ah[2] = f2tf32(f2); al[2] = f2tf32(f2 - __uint_as_float(ah[2]));
            ah[3] = f2tf32(f3); al[3] = f2tf32(f3 - __uint_as_float(ah[3]));

            #pragma unroll
            for (int nt = 0; nt < 8; nt++) {
                int n0 = nt * 8;
                float g0 = Bs[cur][kk + tig    ][n0 + gid];
                float g1 = Bs[cur][kk + tig + 4][n0 + gid];
                uint32_t bh[2], bl[2];
                bh[0] = f2tf32(g0); bl[0] = f2tf32(g0 - __uint_as_float(bh[0]));
                bh[1] = f2tf32(g1); bl[1] = f2tf32(g1 - __uint_as_float(bh[1]));
                mma_tf32(acc[nt], ah, bh);
                mma_tf32(acc[nt], al, bh);
                mma_tf32(acc[nt], ah, bl);
            }
        }

        if (it + 1 < NIT) {
            store_tile(cur ^ 1, (it + 1) * 16);
            __syncthreads();
        }
    }

    int ra_ = row0 + m0 + gid;
    int rb_ = ra_ + 8;
    #pragma unroll
    for (int nt = 0; nt < 8; nt++) {
        int col = nt * 8 + 2 * tig;
        if (ra_ < n_rows)
            *(float2*)&C[(long)ra_ * 64 + col] = make_float2(acc[nt][0], acc[nt][1]);
        if (rb_ < n_rows)
            *(float2*)&C[(long)rb_ * 64 + col] = make_float2(acc[nt][2], acc[nt][3]);
    }
}

// ---------------------------------------------------------------------------
// inputs: x, edge_index(2xE), edge_weight, W1, b1, W2, b2, mask1, mask2
// ---------------------------------------------------------------------------
extern "C" void kernel_launch(void* const* d_in, const int* in_sizes, int n_in,
                              void* d_out, int out_size) {
    const float* x  = (const float*)d_in[0];
    const void* ei  = d_in[1];
    const float* ew = (const float*)d_in[2];
    const float* W1 = (const float*)d_in[3];
    const float* b1 = (const float*)d_in[4];
    const float* W2 = (const float*)d_in[5];
    const float* b2 = (const float*)d_in[6];
    const void* m1  = d_in[7];
    const void* m2  = d_in[8];
    float* out = (float*)d_out;

    int n_nodes = in_sizes[0] / 384;
    int n_edges = in_sizes[2];

    float *H1, *AGG1, *H2;
    cudaGetSymbolAddress((void**)&H1, g_H1);
    cudaGetSymbolAddress((void**)&AGG1, g_AGG1);
    cudaGetSymbolAddress((void**)&H2, g_H2);

    detect_kernel<<<1, 32>>>((const int*)ei, (const unsigned int*)m1);

    // ---- CSR build (once; reused by both layers) ----
    int nb = (n_nodes + 1023) / 1024;
    zero_deg<<<(n_nodes + 255) / 256, 256>>>(n_nodes);
    hist_kernel<<<(n_edges + 255) / 256, 256>>>(ei, n_edges);
    scan1_kernel<<<nb, 1024>>>(n_nodes);
    scan2_kernel<<<1, 32>>>(nb, n_nodes, n_edges);
    scan3_kernel<<<(n_nodes + 255) / 256, 256>>>(n_nodes);
    fill_kernel<<<(n_edges + 255) / 256, 256>>>(ei, ew, n_edges);

    int gb = (n_nodes + 127) / 128;
    int ab = (n_nodes + 7) / 8;
    gemm_tc<384, 0><<<gb, 256>>>(x, m1, W1, nullptr, H1, n_nodes);
    agg_kernel<<<ab, 256>>>(H1, nullptr, AGG1, n_nodes);
    gemm_tc<64, 1><<<gb, 256>>>(AGG1, m2, W2, b1, H2, n_nodes);
    agg_kernel<<<ab, 256>>>(H2, b2, out, n_nodes);
}

// round 13
// speedup vs baseline: 1.4712x; 1.1450x over previous
#include <cuda_runtime.h>
#include <cstdint>

#define D 64
#define NMAX 100000
#define EMAX 1600000

__device__ float g_H1[NMAX * D];
__device__ float g_AGG1[NMAX * D];
__device__ float g_H2[NMAX * D];
__device__ int   g_deg[NMAX];
__device__ int   g_offs[NMAX + 1];
__device__ int   g_cursor[NMAX];
__device__ uint2 g_srcw[EMAX];
__device__ int   g_bsum[128];

// flags[0]: edge_index is int64 (1) or int32 (0)
// flags[1]: mask elem kind: 0 = uint8, 1 = float32, 2 = int32
__device__ int g_flags[2];

// ---- tf32 helpers -----------------------------------------------------------
__device__ __forceinline__ uint32_t f2tf32(float f) {
    uint32_t r;
    asm("cvt.rna.tf32.f32 %0, %1;" : "=r"(r) : "f"(f));
    return r;
}
__device__ __forceinline__ void mma_tf32(float* c, const uint32_t* a, const uint32_t* b) {
    asm volatile(
        "mma.sync.aligned.m16n8k8.row.col.f32.tf32.tf32.f32 "
        "{%0,%1,%2,%3}, {%4,%5,%6,%7}, {%8,%9}, {%0,%1,%2,%3};"
        : "+f"(c[0]), "+f"(c[1]), "+f"(c[2]), "+f"(c[3])
        : "r"(a[0]), "r"(a[1]), "r"(a[2]), "r"(a[3]), "r"(b[0]), "r"(b[1]));
}

// ---------------------------------------------------------------------------
// Dtype detection — warp-parallel.
// ---------------------------------------------------------------------------
__global__ void detect_kernel(const int* __restrict__ ei_words,
                              const unsigned int* __restrict__ mask_words) {
    int lane = threadIdx.x;
    int odd_nonzero = 0;
    #pragma unroll
    for (int i = 0; i < 8; i++)
        if (ei_words[2 * (lane + i * 32) + 1] != 0) odd_nonzero = 1;
    int is64 = !__any_sync(0xFFFFFFFFu, odd_nonzero);

    int saw_f32 = 0, saw_hi = 0;
    #pragma unroll
    for (int i = 0; i < 128; i++) {
        unsigned int w = mask_words[lane + i * 32];
        if (w == 0x3F800000u) saw_f32 = 1;
        if ((w & 0xFFFFFF00u) != 0) saw_hi = 1;
    }
    int any_f32 = __any_sync(0xFFFFFFFFu, saw_f32);
    int any_hi  = __any_sync(0xFFFFFFFFu, saw_hi);
    if (lane == 0) {
        g_flags[0] = is64;
        g_flags[1] = any_f32 ? 1 : (any_hi ? 0 : 2);
    }
}

// ---------------------------------------------------------------------------
// CSR build: zero -> hist -> scan(3) -> fill
// ---------------------------------------------------------------------------
__global__ void zero_deg(int n) {
    int i = blockIdx.x * blockDim.x + threadIdx.x;
    if (i < n) g_deg[i] = 0;
}

__global__ void hist_kernel(const void* __restrict__ ei_raw, int n_edges) {
    int e = blockIdx.x * blockDim.x + threadIdx.x;
    if (e >= n_edges) return;
    int d = g_flags[0] ? (int)((const long long*)ei_raw)[n_edges + e]
                       : ((const int*)ei_raw)[n_edges + e];
    atomicAdd(&g_deg[d], 1);
}

__global__ void scan1_kernel(int n) {
    __shared__ int sh[1024];
    int i = blockIdx.x * 1024 + threadIdx.x;
    int v = (i < n) ? g_deg[i] : 0;
    sh[threadIdx.x] = v;
    __syncthreads();
    #pragma unroll
    for (int off = 1; off < 1024; off <<= 1) {
        int t = (threadIdx.x >= off) ? sh[threadIdx.x - off] : 0;
        __syncthreads();
        sh[threadIdx.x] += t;
        __syncthreads();
    }
    if (i < n) g_offs[i] = sh[threadIdx.x] - v;
    if (threadIdx.x == 1023) g_bsum[blockIdx.x] = sh[1023];
}

__global__ void scan2_kernel(int nb, int n, int n_edges) {
    if (threadIdx.x == 0) {
        int run = 0;
        for (int b = 0; b < nb; b++) { int t = g_bsum[b]; g_bsum[b] = run; run += t; }
        g_offs[n] = n_edges;
    }
}

__global__ void scan3_kernel(int n) {
    int i = blockIdx.x * blockDim.x + threadIdx.x;
    if (i >= n) return;
    int o = g_offs[i] + g_bsum[i >> 10];
    g_offs[i] = o;
    g_cursor[i] = o;
}

__global__ void fill_kernel(const void* __restrict__ ei_raw,
                            const float* __restrict__ ew, int n_edges) {
    int e = blockIdx.x * blockDim.x + threadIdx.x;
    if (e >= n_edges) return;
    int s, d;
    if (g_flags[0]) {
        const long long* ei = (const long long*)ei_raw;
        s = (int)ei[e];
        d = (int)ei[n_edges + e];
    } else {
        const int* ei = (const int*)ei_raw;
        s = ei[e];
        d = ei[n_edges + e];
    }
    int p = atomicAdd(&g_cursor[d], 1);
    g_srcw[p] = make_uint2((unsigned)s, __float_as_uint(__ldg(&ew[e])));
}

// ---------------------------------------------------------------------------
// CSR aggregation: out[node] = sum_{e in in(node)} H[src(e)] * w(e) (+ bias)
// One warp per node, float2 per lane. Unroll 4 for MLP.
// ---------------------------------------------------------------------------
__global__ __launch_bounds__(256) void agg_kernel(
        const float* __restrict__ H,
        const float* __restrict__ bias,
        float* __restrict__ out, int n_nodes) {
    int node = blockIdx.x * 8 + (threadIdx.x >> 5);
    if (node >= n_nodes) return;
    int lane = threadIdx.x & 31;
    int beg = g_offs[node], end = g_offs[node + 1];

    float ax = 0.f, ay = 0.f;
    int e = beg;
    for (; e + 4 <= end; e += 4) {
        uint2 s0 = g_srcw[e],     s1 = g_srcw[e + 1];
        uint2 s2 = g_srcw[e + 2], s3 = g_srcw[e + 3];
        float2 v0 = *(const float2*)&H[(long)s0.x * 64 + lane * 2];
        float2 v1 = *(const float2*)&H[(long)s1.x * 64 + lane * 2];
        float2 v2 = *(const float2*)&H[(long)s2.x * 64 + lane * 2];
        float2 v3 = *(const float2*)&H[(long)s3.x * 64 + lane * 2];
        float w0 = __uint_as_float(s0.y), w1 = __uint_as_float(s1.y);
        float w2 = __uint_as_float(s2.y), w3 = __uint_as_float(s3.y);
        ax = fmaf(v0.x, w0, ax); ay = fmaf(v0.y, w0, ay);
        ax = fmaf(v1.x, w1, ax); ay = fmaf(v1.y, w1, ay);
        ax = fmaf(v2.x, w2, ax); ay = fmaf(v2.y, w2, ay);
        ax = fmaf(v3.x, w3, ax); ay = fmaf(v3.y, w3, ay);
    }
    for (; e < end; e++) {
        uint2 s0 = g_srcw[e];
        float2 v0 = *(const float2*)&H[(long)s0.x * 64 + lane * 2];
        float w0 = __uint_as_float(s0.y);
        ax = fmaf(v0.x, w0, ax); ay = fmaf(v0.y, w0, ay);
    }
    if (bias) {
        ax += __ldg(&bias[lane * 2]);
        ay += __ldg(&bias[lane * 2 + 1]);
    }
    *(float2*)&out[(long)node * 64 + lane * 2] = make_float2(ax, ay);
}

// ---------------------------------------------------------------------------
// Fused GEMM, double-buffered, tf32 tensor-core 2-pass:
//   D = ah*bh + al*bh = a (full fp32) * bh ; dropped term a*bl ~ 1.4e-4 rel.
//   MODE 0: f(a) = mask ? a*2 : 0
//   MODE 1: f(a) = mask ? relu(a + bias[k])*2 : 0
// BM=128, BN=64, BK=16, 256 threads = 8 warps.
// ---------------------------------------------------------------------------
template <int K, int MODE>
__global__ __launch_bounds__(256) void gemm_tc(
        const float* __restrict__ A,
        const void* __restrict__ mask,
        const float* __restrict__ W,
        const float* __restrict__ bias,
        float* __restrict__ C, int n_rows) {
    __shared__ float As[2][128][20];
    __shared__ float Bs[2][16][72];
    __shared__ float sb[64];

    const int tid = threadIdx.x;
    const int mkind = g_flags[1];
    if (MODE == 1) {
        if (tid < 64) sb[tid] = bias[tid];
        __syncthreads();
    }

    const int row0 = blockIdx.x * 128;
    const int warp = tid >> 5;
    const int lane = tid & 31;
    const int gid = lane >> 2;
    const int tig = lane & 3;
    const int m0 = warp * 16;

    int arow[2], aq[2];
    #pragma unroll
    for (int i = 0; i < 2; i++) {
        int lin = tid + i * 256;
        arow[i] = lin >> 2;
        aq[i]   = lin & 3;
    }
    const int bkk = tid >> 4;
    const int bn4 = tid & 15;

    float4 ra[2];
    uint4  rm[2];
    float4 rb;

    auto load_tile = [&](int k0) {
        #pragma unroll
        for (int i = 0; i < 2; i++) {
            int gr = row0 + arow[i];
            ra[i] = make_float4(0.f, 0.f, 0.f, 0.f);
            rm[i] = make_uint4(0u, 0u, 0u, 0u);
            if (gr < n_rows) {
                long gi = (long)gr * K + k0 + aq[i] * 4;
                ra[i] = *(const float4*)&A[gi];
                if (mkind == 0) {
                    rm[i].x = *(const unsigned int*)((const unsigned char*)mask + gi);
                } else if (mkind == 1) {
                    float4 f = *(const float4*)((const float*)mask + gi);
                    rm[i] = make_uint4(__float_as_uint(f.x), __float_as_uint(f.y),
                                       __float_as_uint(f.z), __float_as_uint(f.w));
                } else {
                    rm[i] = *(const uint4*)((const int*)mask + gi);
                }
            }
        }
        rb = *(const float4*)&W[(long)(k0 + bkk) * 64 + bn4 * 4];
    };

    auto store_tile = [&](int buf, int k0) {
        #pragma unroll
        for (int i = 0; i < 2; i++) {
            float4 v = ra[i];
            float mv[4];
            if (mkind == 0) {
                unsigned int mw = rm[i].x;
                mv[0] = (mw & 0x000000FFu) ? 2.f : 0.f;
                mv[1] = (mw & 0x0000FF00u) ? 2.f : 0.f;
                mv[2] = (mw & 0x00FF0000u) ? 2.f : 0.f;
                mv[3] = (mw & 0xFF000000u) ? 2.f : 0.f;
            } else {
                mv[0] = rm[i].x ? 2.f : 0.f;
                mv[1] = rm[i].y ? 2.f : 0.f;
                mv[2] = rm[i].z ? 2.f : 0.f;
                mv[3] = rm[i].w ? 2.f : 0.f;
            }
            if (MODE == 1) {
                int kb = k0 + aq[i] * 4;
                v.x = fmaxf(v.x + sb[kb + 0], 0.f);
                v.y = fmaxf(v.y + sb[kb + 1], 0.f);
                v.z = fmaxf(v.z + sb[kb + 2], 0.f);
                v.w = fmaxf(v.w + sb[kb + 3], 0.f);
            }
            float4 o = make_float4(v.x * mv[0], v.y * mv[1], v.z * mv[2], v.w * mv[3]);
            *(float4*)&As[buf][arow[i]][aq[i] * 4] = o;
        }
        *(float4*)&Bs[buf][bkk][bn4 * 4] = rb;
    };

    float acc[8][4] = {};
    const int NIT = K / 16;

    load_tile(0);
    store_tile(0, 0);
    __syncthreads();

    for (int it = 0; it < NIT; it++) {
        int cur = it & 1;
        if (it + 1 < NIT) load_tile((it + 1) * 16);

        #pragma unroll
        for (int ks = 0; ks < 2; ks++) {
            int kk = ks * 8;
            float f0 = As[cur][m0 + gid    ][kk + tig];
            float f1 = As[cur][m0 + gid + 8][kk + tig];
            float f2 = As[cur][m0 + gid    ][kk + tig + 4];
            float f3 = As[cur][m0 + gid + 8][kk + tig + 4];
            uint32_t ah[4], al[4];
            ah[0] = f2tf32(f0); al[0] = f2tf32(f0 - __uint_as_float(ah[0]));
            ah[1] = f2tf32(f1); al[1] = f2tf32(f1 - __uint_as_float(ah[1]));
            ah[2] = f2tf32(f2); al[2] = f2tf32(f2 - __uint_as_float(ah[2]));
            ah[3] = f2tf32(f3); al[3] = f2tf32(f3 - __uint_as_float(ah[3]));

            #pragma unroll
            for (int nt = 0; nt < 8; nt++) {
                int n0 = nt * 8;
                float g0 = Bs[cur][kk + tig    ][n0 + gid];
                float g1 = Bs[cur][kk + tig + 4][n0 + gid];
                uint32_t bh[2];
                bh[0] = f2tf32(g0);
                bh[1] = f2tf32(g1);
                mma_tf32(acc[nt], ah, bh);   // ah*bh
                mma_tf32(acc[nt], al, bh);   // al*bh  => full-precision a * bh
            }
        }

        if (it + 1 < NIT) {
            store_tile(cur ^ 1, (it + 1) * 16);
            __syncthreads();
        }
    }

    int ra_ = row0 + m0 + gid;
    int rb_ = ra_ + 8;
    #pragma unroll
    for (int nt = 0; nt < 8; nt++) {
        int col = nt * 8 + 2 * tig;
        if (ra_ < n_rows)
            *(float2*)&C[(long)ra_ * 64 + col] = make_float2(acc[nt][0], acc[nt][1]);
        if (rb_ < n_rows)
            *(float2*)&C[(long)rb_ * 64 + col] = make_float2(acc[nt][2], acc[nt][3]);
    }
}

// ---------------------------------------------------------------------------
// inputs: x, edge_index(2xE), edge_weight, W1, b1, W2, b2, mask1, mask2
// ---------------------------------------------------------------------------
extern "C" void kernel_launch(void* const* d_in, const int* in_sizes, int n_in,
                              void* d_out, int out_size) {
    const float* x  = (const float*)d_in[0];
    const void* ei  = d_in[1];
    const float* ew = (const float*)d_in[2];
    const float* W1 = (const float*)d_in[3];
    const float* b1 = (const float*)d_in[4];
    const float* W2 = (const float*)d_in[5];
    const float* b2 = (const float*)d_in[6];
    const void* m1  = d_in[7];
    const void* m2  = d_in[8];
    float* out = (float*)d_out;

    int n_nodes = in_sizes[0] / 384;
    int n_edges = in_sizes[2];

    float *H1, *AGG1, *H2;
    cudaGetSymbolAddress((void**)&H1, g_H1);
    cudaGetSymbolAddress((void**)&AGG1, g_AGG1);
    cudaGetSymbolAddress((void**)&H2, g_H2);

    detect_kernel<<<1, 32>>>((const int*)ei, (const unsigned int*)m1);

    // ---- CSR build (once; reused by both layers) ----
    int nb = (n_nodes + 1023) / 1024;
    zero_deg<<<(n_nodes + 255) / 256, 256>>>(n_nodes);
    hist_kernel<<<(n_edges + 255) / 256, 256>>>(ei, n_edges);
    scan1_kernel<<<nb, 1024>>>(n_nodes);
    scan2_kernel<<<1, 32>>>(nb, n_nodes, n_edges);
    scan3_kernel<<<(n_nodes + 255) / 256, 256>>>(n_nodes);
    fill_kernel<<<(n_edges + 255) / 256, 256>>>(ei, ew, n_edges);

    int gb = (n_nodes + 127) / 128;
    int ab = (n_nodes + 7) / 8;
    gemm_tc<384, 0><<<gb, 256>>>(x, m1, W1, nullptr, H1, n_nodes);
    agg_kernel<<<ab, 256>>>(H1, nullptr, AGG1, n_nodes);
    gemm_tc<64, 1><<<gb, 256>>>(AGG1, m2, W2, b1, H2, n_nodes);
    agg_kernel<<<ab, 256>>>(H2, b2, out, n_nodes);
}

// round 14
// speedup vs baseline: 1.5902x; 1.0809x over previous
#include <cuda_runtime.h>
#include <cstdint>

#define D 64
#define NMAX 100000
#define EMAX 1600000

__device__ float g_H1[NMAX * D];
__device__ float g_AGG1[NMAX * D];
__device__ float g_H2[NMAX * D];
__device__ int   g_deg[NMAX];
__device__ int   g_offs[NMAX + 1];
__device__ int   g_cursor[NMAX];
__device__ uint2 g_srcw[EMAX];
__device__ int   g_bsum[128];

// flags[0]: edge_index is int64 (1) or int32 (0)
// flags[1]: mask elem kind: 0 = uint8, 1 = float32, 2 = int32
__device__ int g_flags[2];

// ---- tf32 helpers -----------------------------------------------------------
__device__ __forceinline__ uint32_t f2tf32(float f) {
    uint32_t r;
    asm("cvt.rna.tf32.f32 %0, %1;" : "=r"(r) : "f"(f));
    return r;
}
__device__ __forceinline__ void mma_tf32(float* c, const uint32_t* a, const uint32_t* b) {
    asm volatile(
        "mma.sync.aligned.m16n8k8.row.col.f32.tf32.tf32.f32 "
        "{%0,%1,%2,%3}, {%4,%5,%6,%7}, {%8,%9}, {%0,%1,%2,%3};"
        : "+f"(c[0]), "+f"(c[1]), "+f"(c[2]), "+f"(c[3])
        : "r"(a[0]), "r"(a[1]), "r"(a[2]), "r"(a[3]), "r"(b[0]), "r"(b[1]));
}

// ---------------------------------------------------------------------------
// Dtype detection — warp-parallel.
// ---------------------------------------------------------------------------
__global__ void detect_kernel(const int* __restrict__ ei_words,
                              const unsigned int* __restrict__ mask_words) {
    int lane = threadIdx.x;
    int odd_nonzero = 0;
    #pragma unroll
    for (int i = 0; i < 8; i++)
        if (ei_words[2 * (lane + i * 32) + 1] != 0) odd_nonzero = 1;
    int is64 = !__any_sync(0xFFFFFFFFu, odd_nonzero);

    int saw_f32 = 0, saw_hi = 0;
    #pragma unroll
    for (int i = 0; i < 128; i++) {
        unsigned int w = mask_words[lane + i * 32];
        if (w == 0x3F800000u) saw_f32 = 1;
        if ((w & 0xFFFFFF00u) != 0) saw_hi = 1;
    }
    int any_f32 = __any_sync(0xFFFFFFFFu, saw_f32);
    int any_hi  = __any_sync(0xFFFFFFFFu, saw_hi);
    if (lane == 0) {
        g_flags[0] = is64;
        g_flags[1] = any_f32 ? 1 : (any_hi ? 0 : 2);
    }
}

// ---------------------------------------------------------------------------
// CSR build: zero -> hist -> scan(3) -> fill
// ---------------------------------------------------------------------------
__global__ void zero_deg(int n) {
    int i = blockIdx.x * blockDim.x + threadIdx.x;
    if (i < n) g_deg[i] = 0;
}

__global__ void hist_kernel(const void* __restrict__ ei_raw, int n_edges) {
    int e = blockIdx.x * blockDim.x + threadIdx.x;
    if (e >= n_edges) return;
    int d = g_flags[0] ? (int)((const long long*)ei_raw)[n_edges + e]
                       : ((const int*)ei_raw)[n_edges + e];
    atomicAdd(&g_deg[d], 1);
}

__global__ void scan1_kernel(int n) {
    __shared__ int sh[1024];
    int i = blockIdx.x * 1024 + threadIdx.x;
    int v = (i < n) ? g_deg[i] : 0;
    sh[threadIdx.x] = v;
    __syncthreads();
    #pragma unroll
    for (int off = 1; off < 1024; off <<= 1) {
        int t = (threadIdx.x >= off) ? sh[threadIdx.x - off] : 0;
        __syncthreads();
        sh[threadIdx.x] += t;
        __syncthreads();
    }
    if (i < n) g_offs[i] = sh[threadIdx.x] - v;
    if (threadIdx.x == 1023) g_bsum[blockIdx.x] = sh[1023];
}

__global__ void scan2_kernel(int nb, int n, int n_edges) {
    if (threadIdx.x == 0) {
        int run = 0;
        for (int b = 0; b < nb; b++) { int t = g_bsum[b]; g_bsum[b] = run; run += t; }
        g_offs[n] = n_edges;
    }
}

__global__ void scan3_kernel(int n) {
    int i = blockIdx.x * blockDim.x + threadIdx.x;
    if (i >= n) return;
    int o = g_offs[i] + g_bsum[i >> 10];
    g_offs[i] = o;
    g_cursor[i] = o;
}

__global__ void fill_kernel(const void* __restrict__ ei_raw,
                            const float* __restrict__ ew, int n_edges) {
    int e = blockIdx.x * blockDim.x + threadIdx.x;
    if (e >= n_edges) return;
    int s, d;
    if (g_flags[0]) {
        const long long* ei = (const long long*)ei_raw;
        s = (int)ei[e];
        d = (int)ei[n_edges + e];
    } else {
        const int* ei = (const int*)ei_raw;
        s = ei[e];
        d = ei[n_edges + e];
    }
    int p = atomicAdd(&g_cursor[d], 1);
    g_srcw[p] = make_uint2((unsigned)s, __float_as_uint(__ldg(&ew[e])));
}

// ---------------------------------------------------------------------------
// CSR aggregation: out[node] = sum_{e in in(node)} H[src(e)] * w(e) (+ bias)
// One warp per node, float2 per lane. Unroll 4 for MLP.
// ---------------------------------------------------------------------------
__global__ __launch_bounds__(256) void agg_kernel(
        const float* __restrict__ H,
        const float* __restrict__ bias,
        float* __restrict__ out, int n_nodes) {
    int node = blockIdx.x * 8 + (threadIdx.x >> 5);
    if (node >= n_nodes) return;
    int lane = threadIdx.x & 31;
    int beg = g_offs[node], end = g_offs[node + 1];

    float ax = 0.f, ay = 0.f;
    int e = beg;
    for (; e + 4 <= end; e += 4) {
        uint2 s0 = g_srcw[e],     s1 = g_srcw[e + 1];
        uint2 s2 = g_srcw[e + 2], s3 = g_srcw[e + 3];
        float2 v0 = *(const float2*)&H[(long)s0.x * 64 + lane * 2];
        float2 v1 = *(const float2*)&H[(long)s1.x * 64 + lane * 2];
        float2 v2 = *(const float2*)&H[(long)s2.x * 64 + lane * 2];
        float2 v3 = *(const float2*)&H[(long)s3.x * 64 + lane * 2];
        float w0 = __uint_as_float(s0.y), w1 = __uint_as_float(s1.y);
        float w2 = __uint_as_float(s2.y), w3 = __uint_as_float(s3.y);
        ax = fmaf(v0.x, w0, ax); ay = fmaf(v0.y, w0, ay);
        ax = fmaf(v1.x, w1, ax); ay = fmaf(v1.y, w1, ay);
        ax = fmaf(v2.x, w2, ax); ay = fmaf(v2.y, w2, ay);
        ax = fmaf(v3.x, w3, ax); ay = fmaf(v3.y, w3, ay);
    }
    for (; e < end; e++) {
        uint2 s0 = g_srcw[e];
        float2 v0 = *(const float2*)&H[(long)s0.x * 64 + lane * 2];
        float w0 = __uint_as_float(s0.y);
        ax = fmaf(v0.x, w0, ax); ay = fmaf(v0.y, w0, ay);
    }
    if (bias) {
        ax += __ldg(&bias[lane * 2]);
        ay += __ldg(&bias[lane * 2 + 1]);
    }
    *(float2*)&out[(long)node * 64 + lane * 2] = make_float2(ax, ay);
}

// ---------------------------------------------------------------------------
// Fused GEMM, double-buffered, tf32 tensor-core 1-pass (ah*bh):
//   dropped terms al*b + ah*bl ~ 3.4e-4 rel (calibrated vs 2-pass = 2.4e-4).
//   MODE 0: f(a) = mask ? a*2 : 0
//   MODE 1: f(a) = mask ? relu(a + bias[k])*2 : 0
// BM=128, BN=64, BK=16, 256 threads = 8 warps.
// ---------------------------------------------------------------------------
template <int K, int MODE>
__global__ __launch_bounds__(256) void gemm_tc(
        const float* __restrict__ A,
        const void* __restrict__ mask,
        const float* __restrict__ W,
        const float* __restrict__ bias,
        float* __restrict__ C, int n_rows) {
    __shared__ float As[2][128][20];
    __shared__ float Bs[2][16][72];
    __shared__ float sb[64];

    const int tid = threadIdx.x;
    const int mkind = g_flags[1];
    if (MODE == 1) {
        if (tid < 64) sb[tid] = bias[tid];
        __syncthreads();
    }

    const int row0 = blockIdx.x * 128;
    const int warp = tid >> 5;
    const int lane = tid & 31;
    const int gid = lane >> 2;
    const int tig = lane & 3;
    const int m0 = warp * 16;

    int arow[2], aq[2];
    #pragma unroll
    for (int i = 0; i < 2; i++) {
        int lin = tid + i * 256;
        arow[i] = lin >> 2;
        aq[i]   = lin & 3;
    }
    const int bkk = tid >> 4;
    const int bn4 = tid & 15;

    float4 ra[2];
    uint4  rm[2];
    float4 rb;

    auto load_tile = [&](int k0) {
        #pragma unroll
        for (int i = 0; i < 2; i++) {
            int gr = row0 + arow[i];
            ra[i] = make_float4(0.f, 0.f, 0.f, 0.f);
            rm[i] = make_uint4(0u, 0u, 0u, 0u);
            if (gr < n_rows) {
                long gi = (long)gr * K + k0 + aq[i] * 4;
                ra[i] = *(const float4*)&A[gi];
                if (mkind == 0) {
                    rm[i].x = *(const unsigned int*)((const unsigned char*)mask + gi);
                } else if (mkind == 1) {
                    float4 f = *(const float4*)((const float*)mask + gi);
                    rm[i] = make_uint4(__float_as_uint(f.x), __float_as_uint(f.y),
                                       __float_as_uint(f.z), __float_as_uint(f.w));
                } else {
                    rm[i] = *(const uint4*)((const int*)mask + gi);
                }
            }
        }
        rb = *(const float4*)&W[(long)(k0 + bkk) * 64 + bn4 * 4];
    };

    auto store_tile = [&](int buf, int k0) {
        #pragma unroll
        for (int i = 0; i < 2; i++) {
            float4 v = ra[i];
            float mv[4];
            if (mkind == 0) {
                unsigned int mw = rm[i].x;
                mv[0] = (mw & 0x000000FFu) ? 2.f : 0.f;
                mv[1] = (mw & 0x0000FF00u) ? 2.f : 0.f;
                mv[2] = (mw & 0x00FF0000u) ? 2.f : 0.f;
                mv[3] = (mw & 0xFF000000u) ? 2.f : 0.f;
            } else {
                mv[0] = rm[i].x ? 2.f : 0.f;
                mv[1] = rm[i].y ? 2.f : 0.f;
                mv[2] = rm[i].z ? 2.f : 0.f;
                mv[3] = rm[i].w ? 2.f : 0.f;
            }
            if (MODE == 1) {
                int kb = k0 + aq[i] * 4;
                v.x = fmaxf(v.x + sb[kb + 0], 0.f);
                v.y = fmaxf(v.y + sb[kb + 1], 0.f);
                v.z = fmaxf(v.z + sb[kb + 2], 0.f);
                v.w = fmaxf(v.w + sb[kb + 3], 0.f);
            }
            float4 o = make_float4(v.x * mv[0], v.y * mv[1], v.z * mv[2], v.w * mv[3]);
            *(float4*)&As[buf][arow[i]][aq[i] * 4] = o;
        }
        *(float4*)&Bs[buf][bkk][bn4 * 4] = rb;
    };

    float acc[8][4] = {};
    const int NIT = K / 16;

    load_tile(0);
    store_tile(0, 0);
    __syncthreads();

    for (int it = 0; it < NIT; it++) {
        int cur = it & 1;
        if (it + 1 < NIT) load_tile((it + 1) * 16);

        #pragma unroll
        for (int ks = 0; ks < 2; ks++) {
            int kk = ks * 8;
            uint32_t ah[4];
            ah[0] = f2tf32(As[cur][m0 + gid    ][kk + tig]);
            ah[1] = f2tf32(As[cur][m0 + gid + 8][kk + tig]);
            ah[2] = f2tf32(As[cur][m0 + gid    ][kk + tig + 4]);
            ah[3] = f2tf32(As[cur][m0 + gid + 8][kk + tig + 4]);

            #pragma unroll
            for (int nt = 0; nt < 8; nt++) {
                int n0 = nt * 8;
                uint32_t bh[2];
                bh[0] = f2tf32(Bs[cur][kk + tig    ][n0 + gid]);
                bh[1] = f2tf32(Bs[cur][kk + tig + 4][n0 + gid]);
                mma_tf32(acc[nt], ah, bh);
            }
        }

        if (it + 1 < NIT) {
            store_tile(cur ^ 1, (it + 1) * 16);
            __syncthreads();
        }
    }

    int ra_ = row0 + m0 + gid;
    int rb_ = ra_ + 8;
    #pragma unroll
    for (int nt = 0; nt < 8; nt++) {
        int col = nt * 8 + 2 * tig;
        if (ra_ < n_rows)
            *(float2*)&C[(long)ra_ * 64 + col] = make_float2(acc[nt][0], acc[nt][1]);
        if (rb_ < n_rows)
            *(float2*)&C[(long)rb_ * 64 + col] = make_float2(acc[nt][2], acc[nt][3]);
    }
}

// ---------------------------------------------------------------------------
// inputs: x, edge_index(2xE), edge_weight, W1, b1, W2, b2, mask1, mask2
// ---------------------------------------------------------------------------
extern "C" void kernel_launch(void* const* d_in, const int* in_sizes, int n_in,
                              void* d_out, int out_size) {
    const float* x  = (const float*)d_in[0];
    const void* ei  = d_in[1];
    const float* ew = (const float*)d_in[2];
    const float* W1 = (const float*)d_in[3];
    const float* b1 = (const float*)d_in[4];
    const float* W2 = (const float*)d_in[5];
    const float* b2 = (const float*)d_in[6];
    const void* m1  = d_in[7];
    const void* m2  = d_in[8];
    float* out = (float*)d_out;

    int n_nodes = in_sizes[0] / 384;
    int n_edges = in_sizes[2];

    float *H1, *AGG1, *H2;
    cudaGetSymbolAddress((void**)&H1, g_H1);
    cudaGetSymbolAddress((void**)&AGG1, g_AGG1);
    cudaGetSymbolAddress((void**)&H2, g_H2);

    detect_kernel<<<1, 32>>>((const int*)ei, (const unsigned int*)m1);

    // ---- CSR build (once; reused by both layers) ----
    int nb = (n_nodes + 1023) / 1024;
    zero_deg<<<(n_nodes + 255) / 256, 256>>>(n_nodes);
    hist_kernel<<<(n_edges + 255) / 256, 256>>>(ei, n_edges);
    scan1_kernel<<<nb, 1024>>>(n_nodes);
    scan2_kernel<<<1, 32>>>(nb, n_nodes, n_edges);
    scan3_kernel<<<(n_nodes + 255) / 256, 256>>>(n_nodes);
    fill_kernel<<<(n_edges + 255) / 256, 256>>>(ei, ew, n_edges);

    int gb = (n_nodes + 127) / 128;
    int ab = (n_nodes + 7) / 8;
    gemm_tc<384, 0><<<gb, 256>>>(x, m1, W1, nullptr, H1, n_nodes);
    agg_kernel<<<ab, 256>>>(H1, nullptr, AGG1, n_nodes);
    gemm_tc<64, 1><<<gb, 256>>>(AGG1, m2, W2, b1, H2, n_nodes);
    agg_kernel<<<ab, 256>>>(H2, b2, out, n_nodes);
}

// round 15
// speedup vs baseline: 1.6091x; 1.0119x over previous
#include <cuda_runtime.h>
#include <cstdint>

#define D 64
#define NMAX 100000
#define EMAX 1600000

__device__ float g_H1[NMAX * D];
__device__ float g_AGG1[NMAX * D];
__device__ float g_H2[NMAX * D];
__device__ int   g_deg[NMAX];
__device__ int   g_offs[NMAX + 1];
__device__ int   g_cursor[NMAX];
__device__ uint2 g_srcw[EMAX];
__device__ int   g_bsum[128];

// flags[0]: edge_index is int64 (1) or int32 (0)
// flags[1]: mask elem kind: 0 = uint8, 1 = float32, 2 = int32
__device__ int g_flags[2];

// ---- tf32 helpers -----------------------------------------------------------
__device__ __forceinline__ uint32_t f2tf32(float f) {
    uint32_t r;
    asm("cvt.rna.tf32.f32 %0, %1;" : "=r"(r) : "f"(f));
    return r;
}
__device__ __forceinline__ void mma_tf32(float* c, const uint32_t* a, const uint32_t* b) {
    asm volatile(
        "mma.sync.aligned.m16n8k8.row.col.f32.tf32.tf32.f32 "
        "{%0,%1,%2,%3}, {%4,%5,%6,%7}, {%8,%9}, {%0,%1,%2,%3};"
        : "+f"(c[0]), "+f"(c[1]), "+f"(c[2]), "+f"(c[3])
        : "r"(a[0]), "r"(a[1]), "r"(a[2]), "r"(a[3]), "r"(b[0]), "r"(b[1]));
}

// ---------------------------------------------------------------------------
// Dtype detection — warp-parallel.
// ---------------------------------------------------------------------------
__global__ void detect_kernel(const int* __restrict__ ei_words,
                              const unsigned int* __restrict__ mask_words) {
    int lane = threadIdx.x;
    int odd_nonzero = 0;
    #pragma unroll
    for (int i = 0; i < 8; i++)
        if (ei_words[2 * (lane + i * 32) + 1] != 0) odd_nonzero = 1;
    int is64 = !__any_sync(0xFFFFFFFFu, odd_nonzero);

    int saw_f32 = 0, saw_hi = 0;
    #pragma unroll
    for (int i = 0; i < 128; i++) {
        unsigned int w = mask_words[lane + i * 32];
        if (w == 0x3F800000u) saw_f32 = 1;
        if ((w & 0xFFFFFF00u) != 0) saw_hi = 1;
    }
    int any_f32 = __any_sync(0xFFFFFFFFu, saw_f32);
    int any_hi  = __any_sync(0xFFFFFFFFu, saw_hi);
    if (lane == 0) {
        g_flags[0] = is64;
        g_flags[1] = any_f32 ? 1 : (any_hi ? 0 : 2);
    }
}

// ---------------------------------------------------------------------------
// CSR build: zero -> hist -> scan(3) -> fill
// ---------------------------------------------------------------------------
__global__ void zero_deg(int n) {
    int i = blockIdx.x * blockDim.x + threadIdx.x;
    if (i < n) g_deg[i] = 0;
}

__global__ void hist_kernel(const void* __restrict__ ei_raw, int n_edges) {
    int e = blockIdx.x * blockDim.x + threadIdx.x;
    if (e >= n_edges) return;
    int d = g_flags[0] ? (int)((const long long*)ei_raw)[n_edges + e]
                       : ((const int*)ei_raw)[n_edges + e];
    atomicAdd(&g_deg[d], 1);
}

__global__ void scan1_kernel(int n) {
    __shared__ int sh[1024];
    int i = blockIdx.x * 1024 + threadIdx.x;
    int v = (i < n) ? g_deg[i] : 0;
    sh[threadIdx.x] = v;
    __syncthreads();
    #pragma unroll
    for (int off = 1; off < 1024; off <<= 1) {
        int t = (threadIdx.x >= off) ? sh[threadIdx.x - off] : 0;
        __syncthreads();
        sh[threadIdx.x] += t;
        __syncthreads();
    }
    if (i < n) g_offs[i] = sh[threadIdx.x] - v;
    if (threadIdx.x == 1023) g_bsum[blockIdx.x] = sh[1023];
}

__global__ void scan2_kernel(int nb, int n, int n_edges) {
    if (threadIdx.x == 0) {
        int run = 0;
        for (int b = 0; b < nb; b++) { int t = g_bsum[b]; g_bsum[b] = run; run += t; }
        g_offs[n] = n_edges;
    }
}

__global__ void scan3_kernel(int n) {
    int i = blockIdx.x * blockDim.x + threadIdx.x;
    if (i >= n) return;
    int o = g_offs[i] + g_bsum[i >> 10];
    g_offs[i] = o;
    g_cursor[i] = o;
}

__global__ void fill_kernel(const void* __restrict__ ei_raw,
                            const float* __restrict__ ew, int n_edges) {
    int e = blockIdx.x * blockDim.x + threadIdx.x;
    if (e >= n_edges) return;
    int s, d;
    if (g_flags[0]) {
        const long long* ei = (const long long*)ei_raw;
        s = (int)ei[e];
        d = (int)ei[n_edges + e];
    } else {
        const int* ei = (const int*)ei_raw;
        s = ei[e];
        d = ei[n_edges + e];
    }
    int p = atomicAdd(&g_cursor[d], 1);
    g_srcw[p] = make_uint2((unsigned)s, __float_as_uint(__ldg(&ew[e])));
}

// ---------------------------------------------------------------------------
// CSR aggregation: out[node] = sum_{e in in(node)} H[src(e)] * w(e) (+ bias)
// One warp per node; two half-warps process two edges concurrently,
// 16 lanes x float4 each (LDG.128). Halves merged via shfl at the end.
// ---------------------------------------------------------------------------
__global__ __launch_bounds__(256) void agg_kernel(
        const float* __restrict__ H,
        const float* __restrict__ bias,
        float* __restrict__ out, int n_nodes) {
    int node = blockIdx.x * 8 + (threadIdx.x >> 5);
    if (node >= n_nodes) return;
    int lane = threadIdx.x & 31;
    int half = lane >> 4;      // 0/1: which edge of the pair
    int li = lane & 15;        // column group: cols li*4 .. li*4+3
    int beg = g_offs[node], end = g_offs[node + 1];

    float4 acc = make_float4(0.f, 0.f, 0.f, 0.f);
    int e = beg + half;
    // 2x unrolled over edge pairs (4 edges per iteration across both halves)
    for (; e + 2 < end; e += 4) {
        uint2 s0 = g_srcw[e];
        uint2 s1 = g_srcw[e + 2];
        float4 v0 = *(const float4*)&H[(long)s0.x * 64 + li * 4];
        float4 v1 = *(const float4*)&H[(long)s1.x * 64 + li * 4];
        float w0 = __uint_as_float(s0.y);
        float w1 = __uint_as_float(s1.y);
        acc.x = fmaf(v0.x, w0, acc.x); acc.y = fmaf(v0.y, w0, acc.y);
        acc.z = fmaf(v0.z, w0, acc.z); acc.w = fmaf(v0.w, w0, acc.w);
        acc.x = fmaf(v1.x, w1, acc.x); acc.y = fmaf(v1.y, w1, acc.y);
        acc.z = fmaf(v1.z, w1, acc.z); acc.w = fmaf(v1.w, w1, acc.w);
    }
    if (e < end) {
        uint2 s0 = g_srcw[e];
        float4 v0 = *(const float4*)&H[(long)s0.x * 64 + li * 4];
        float w0 = __uint_as_float(s0.y);
        acc.x = fmaf(v0.x, w0, acc.x); acc.y = fmaf(v0.y, w0, acc.y);
        acc.z = fmaf(v0.z, w0, acc.z); acc.w = fmaf(v0.w, w0, acc.w);
    }

    // merge the two halves (lane i += lane i+16)
    const unsigned fm = 0xFFFFFFFFu;
    acc.x += __shfl_down_sync(fm, acc.x, 16);
    acc.y += __shfl_down_sync(fm, acc.y, 16);
    acc.z += __shfl_down_sync(fm, acc.z, 16);
    acc.w += __shfl_down_sync(fm, acc.w, 16);

    if (half == 0) {
        if (bias) {
            float4 b = __ldg((const float4*)&bias[li * 4]);
            acc.x += b.x; acc.y += b.y; acc.z += b.z; acc.w += b.w;
        }
        *(float4*)&out[(long)node * 64 + li * 4] = acc;
    }
}

// ---------------------------------------------------------------------------
// Fused GEMM, double-buffered, tf32 tensor-core 1-pass (ah*bh), ~3e-4 rel.
//   MODE 0: f(a) = mask ? a*2 : 0
//   MODE 1: f(a) = mask ? relu(a + bias[k])*2 : 0
// BM=128, BN=64, BK=16, 256 threads = 8 warps.
// ---------------------------------------------------------------------------
template <int K, int MODE>
__global__ __launch_bounds__(256) void gemm_tc(
        const float* __restrict__ A,
        const void* __restrict__ mask,
        const float* __restrict__ W,
        const float* __restrict__ bias,
        float* __restrict__ C, int n_rows) {
    __shared__ float As[2][128][20];
    __shared__ float Bs[2][16][72];
    __shared__ float sb[64];

    const int tid = threadIdx.x;
    const int mkind = g_flags[1];
    if (MODE == 1) {
        if (tid < 64) sb[tid] = bias[tid];
        __syncthreads();
    }

    const int row0 = blockIdx.x * 128;
    const int warp = tid >> 5;
    const int lane = tid & 31;
    const int gid = lane >> 2;
    const int tig = lane & 3;
    const int m0 = warp * 16;

    int arow[2], aq[2];
    #pragma unroll
    for (int i = 0; i < 2; i++) {
        int lin = tid + i * 256;
        arow[i] = lin >> 2;
        aq[i]   = lin & 3;
    }
    const int bkk = tid >> 4;
    const int bn4 = tid & 15;

    float4 ra[2];
    uint4  rm[2];
    float4 rb;

    auto load_tile = [&](int k0) {
        #pragma unroll
        for (int i = 0; i < 2; i++) {
            int gr = row0 + arow[i];
            ra[i] = make_float4(0.f, 0.f, 0.f, 0.f);
            rm[i] = make_uint4(0u, 0u, 0u, 0u);
            if (gr < n_rows) {
                long gi = (long)gr * K + k0 + aq[i] * 4;
                ra[i] = *(const float4*)&A[gi];
                if (mkind == 0) {
                    rm[i].x = *(const unsigned int*)((const unsigned char*)mask + gi);
                } else if (mkind == 1) {
                    float4 f = *(const float4*)((const float*)mask + gi);
                    rm[i] = make_uint4(__float_as_uint(f.x), __float_as_uint(f.y),
                                       __float_as_uint(f.z), __float_as_uint(f.w));
                } else {
                    rm[i] = *(const uint4*)((const int*)mask + gi);
                }
            }
        }
        rb = *(const float4*)&W[(long)(k0 + bkk) * 64 + bn4 * 4];
    };

    auto store_tile = [&](int buf, int k0) {
        #pragma unroll
        for (int i = 0; i < 2; i++) {
            float4 v = ra[i];
            float mv[4];
            if (mkind == 0) {
                unsigned int mw = rm[i].x;
                mv[0] = (mw & 0x000000FFu) ? 2.f : 0.f;
                mv[1] = (mw & 0x0000FF00u) ? 2.f : 0.f;
                mv[2] = (mw & 0x00FF0000u) ? 2.f : 0.f;
                mv[3] = (mw & 0xFF000000u) ? 2.f : 0.f;
            } else {
                mv[0] = rm[i].x ? 2.f : 0.f;
                mv[1] = rm[i].y ? 2.f : 0.f;
                mv[2] = rm[i].z ? 2.f : 0.f;
                mv[3] = rm[i].w ? 2.f : 0.f;
            }
            if (MODE == 1) {
                int kb = k0 + aq[i] * 4;
                v.x = fmaxf(v.x + sb[kb + 0], 0.f);
                v.y = fmaxf(v.y + sb[kb + 1], 0.f);
                v.z = fmaxf(v.z + sb[kb + 2], 0.f);
                v.w = fmaxf(v.w + sb[kb + 3], 0.f);
            }
            float4 o = make_float4(v.x * mv[0], v.y * mv[1], v.z * mv[2], v.w * mv[3]);
            *(float4*)&As[buf][arow[i]][aq[i] * 4] = o;
        }
        *(float4*)&Bs[buf][bkk][bn4 * 4] = rb;
    };

    float acc[8][4] = {};
    const int NIT = K / 16;

    load_tile(0);
    store_tile(0, 0);
    __syncthreads();

    for (int it = 0; it < NIT; it++) {
        int cur = it & 1;
        if (it + 1 < NIT) load_tile((it + 1) * 16);

        #pragma unroll
        for (int ks = 0; ks < 2; ks++) {
            int kk = ks * 8;
            uint32_t ah[4];
            ah[0] = f2tf32(As[cur][m0 + gid    ][kk + tig]);
            ah[1] = f2tf32(As[cur][m0 + gid + 8][kk + tig]);
            ah[2] = f2tf32(As[cur][m0 + gid    ][kk + tig + 4]);
            ah[3] = f2tf32(As[cur][m0 + gid + 8][kk + tig + 4]);

            #pragma unroll
            for (int nt = 0; nt < 8; nt++) {
                int n0 = nt * 8;
                uint32_t bh[2];
                bh[0] = f2tf32(Bs[cur][kk + tig    ][n0 + gid]);
                bh[1] = f2tf32(Bs[cur][kk + tig + 4][n0 + gid]);
                mma_tf32(acc[nt], ah, bh);
            }
        }

        if (it + 1 < NIT) {
            store_tile(cur ^ 1, (it + 1) * 16);
            __syncthreads();
        }
    }

    int ra_ = row0 + m0 + gid;
    int rb_ = ra_ + 8;
    #pragma unroll
    for (int nt = 0; nt < 8; nt++) {
        int col = nt * 8 + 2 * tig;
        if (ra_ < n_rows)
            *(float2*)&C[(long)ra_ * 64 + col] = make_float2(acc[nt][0], acc[nt][1]);
        if (rb_ < n_rows)
            *(float2*)&C[(long)rb_ * 64 + col] = make_float2(acc[nt][2], acc[nt][3]);
    }
}

// ---------------------------------------------------------------------------
// inputs: x, edge_index(2xE), edge_weight, W1, b1, W2, b2, mask1, mask2
// ---------------------------------------------------------------------------
extern "C" void kernel_launch(void* const* d_in, const int* in_sizes, int n_in,
                              void* d_out, int out_size) {
    const float* x  = (const float*)d_in[0];
    const void* ei  = d_in[1];
    const float* ew = (const float*)d_in[2];
    const float* W1 = (const float*)d_in[3];
    const float* b1 = (const float*)d_in[4];
    const float* W2 = (const float*)d_in[5];
    const float* b2 = (const float*)d_in[6];
    const void* m1  = d_in[7];
    const void* m2  = d_in[8];
    float* out = (float*)d_out;

    int n_nodes = in_sizes[0] / 384;
    int n_edges = in_sizes[2];

    float *H1, *AGG1, *H2;
    cudaGetSymbolAddress((void**)&H1, g_H1);
    cudaGetSymbolAddress((void**)&AGG1, g_AGG1);
    cudaGetSymbolAddress((void**)&H2, g_H2);

    detect_kernel<<<1, 32>>>((const int*)ei, (const unsigned int*)m1);

    // ---- CSR build (once; reused by both layers) ----
    int nb = (n_nodes + 1023) / 1024;
    zero_deg<<<(n_nodes + 255) / 256, 256>>>(n_nodes);
    hist_kernel<<<(n_edges + 255) / 256, 256>>>(ei, n_edges);
    scan1_kernel<<<nb, 1024>>>(n_nodes);
    scan2_kernel<<<1, 32>>>(nb, n_nodes, n_edges);
    scan3_kernel<<<(n_nodes + 255) / 256, 256>>>(n_nodes);
    fill_kernel<<<(n_edges + 255) / 256, 256>>>(ei, ew, n_edges);

    int gb = (n_nodes + 127) / 128;
    int ab = (n_nodes + 7) / 8;
    gemm_tc<384, 0><<<gb, 256>>>(x, m1, W1, nullptr, H1, n_nodes);
    agg_kernel<<<ab, 256>>>(H1, nullptr, AGG1, n_nodes);
    gemm_tc<64, 1><<<gb, 256>>>(AGG1, m2, W2, b1, H2, n_nodes);
    agg_kernel<<<ab, 256>>>(H2, b2, out, n_nodes);
}

// round 16
// speedup vs baseline: 1.7950x; 1.1155x over previous
#include <cuda_runtime.h>
#include <cstdint>

#define D 64
#define NMAX 100000
#define EMAX 1600000

__device__ float g_H1[NMAX * D];
__device__ float g_AGG1[NMAX * D];
__device__ float g_H2[NMAX * D];
__device__ int   g_deg[NMAX];
__device__ int   g_offs[NMAX + 1];
__device__ int   g_cursor[NMAX];
__device__ uint2 g_srcw[EMAX];
__device__ int   g_bsum[128];

// flags[0]: edge_index is int64 (1) or int32 (0)
// flags[1]: mask elem kind: 0 = uint8, 1 = float32, 2 = int32
__device__ int g_flags[2];

// ---- tf32 helpers -----------------------------------------------------------
__device__ __forceinline__ uint32_t f2tf32(float f) {
    uint32_t r;
    asm("cvt.rna.tf32.f32 %0, %1;" : "=r"(r) : "f"(f));
    return r;
}
__device__ __forceinline__ void mma_tf32(float* c, const uint32_t* a, const uint32_t* b) {
    asm volatile(
        "mma.sync.aligned.m16n8k8.row.col.f32.tf32.tf32.f32 "
        "{%0,%1,%2,%3}, {%4,%5,%6,%7}, {%8,%9}, {%0,%1,%2,%3};"
        : "+f"(c[0]), "+f"(c[1]), "+f"(c[2]), "+f"(c[3])
        : "r"(a[0]), "r"(a[1]), "r"(a[2]), "r"(a[3]), "r"(b[0]), "r"(b[1]));
}

// ---------------------------------------------------------------------------
// Dtype detection — warp-parallel.
// ---------------------------------------------------------------------------
__global__ void detect_kernel(const int* __restrict__ ei_words,
                              const unsigned int* __restrict__ mask_words) {
    int lane = threadIdx.x;
    int odd_nonzero = 0;
    #pragma unroll
    for (int i = 0; i < 8; i++)
        if (ei_words[2 * (lane + i * 32) + 1] != 0) odd_nonzero = 1;
    int is64 = !__any_sync(0xFFFFFFFFu, odd_nonzero);

    int saw_f32 = 0, saw_hi = 0;
    #pragma unroll
    for (int i = 0; i < 128; i++) {
        unsigned int w = mask_words[lane + i * 32];
        if (w == 0x3F800000u) saw_f32 = 1;
        if ((w & 0xFFFFFF00u) != 0) saw_hi = 1;
    }
    int any_f32 = __any_sync(0xFFFFFFFFu, saw_f32);
    int any_hi  = __any_sync(0xFFFFFFFFu, saw_hi);
    if (lane == 0) {
        g_flags[0] = is64;
        g_flags[1] = any_f32 ? 1 : (any_hi ? 0 : 2);
    }
}

// ---------------------------------------------------------------------------
// CSR build: zero -> hist -> scan(3) -> fill
// ---------------------------------------------------------------------------
__global__ void zero_deg(int n) {
    int i = blockIdx.x * blockDim.x + threadIdx.x;
    if (i < n) g_deg[i] = 0;
}

__global__ void hist_kernel(const void* __restrict__ ei_raw, int n_edges) {
    int e = blockIdx.x * blockDim.x + threadIdx.x;
    if (e >= n_edges) return;
    int d = g_flags[0] ? (int)((const long long*)ei_raw)[n_edges + e]
                       : ((const int*)ei_raw)[n_edges + e];
    atomicAdd(&g_deg[d], 1);
}

__global__ void scan1_kernel(int n) {
    __shared__ int sh[1024];
    int i = blockIdx.x * 1024 + threadIdx.x;
    int v = (i < n) ? g_deg[i] : 0;
    sh[threadIdx.x] = v;
    __syncthreads();
    #pragma unroll
    for (int off = 1; off < 1024; off <<= 1) {
        int t = (threadIdx.x >= off) ? sh[threadIdx.x - off] : 0;
        __syncthreads();
        sh[threadIdx.x] += t;
        __syncthreads();
    }
    if (i < n) g_offs[i] = sh[threadIdx.x] - v;
    if (threadIdx.x == 1023) g_bsum[blockIdx.x] = sh[1023];
}

__global__ void scan2_kernel(int nb, int n, int n_edges) {
    if (threadIdx.x == 0) {
        int run = 0;
        for (int b = 0; b < nb; b++) { int t = g_bsum[b]; g_bsum[b] = run; run += t; }
        g_offs[n] = n_edges;
    }
}

__global__ void scan3_kernel(int n) {
    int i = blockIdx.x * blockDim.x + threadIdx.x;
    if (i >= n) return;
    int o = g_offs[i] + g_bsum[i >> 10];
    g_offs[i] = o;
    g_cursor[i] = o;
}

__global__ void fill_kernel(const void* __restrict__ ei_raw,
                            const float* __restrict__ ew, int n_edges) {
    int e = blockIdx.x * blockDim.x + threadIdx.x;
    if (e >= n_edges) return;
    int s, d;
    if (g_flags[0]) {
        const long long* ei = (const long long*)ei_raw;
        s = (int)ei[e];
        d = (int)ei[n_edges + e];
    } else {
        const int* ei = (const int*)ei_raw;
        s = ei[e];
        d = ei[n_edges + e];
    }
    int p = atomicAdd(&g_cursor[d], 1);
    g_srcw[p] = make_uint2((unsigned)s, __float_as_uint(__ldg(&ew[e])));
}

// ---------------------------------------------------------------------------
// CSR aggregation: out[node] = sum_{e in in(node)} H[src(e)] * w(e) (+ bias)
// One warp per node; two half-warps, 16 lanes x float4, 4 edges in flight
// per half (8 per warp). Halves merged via shfl.
// ---------------------------------------------------------------------------
__global__ __launch_bounds__(256) void agg_kernel(
        const float* __restrict__ H,
        const float* __restrict__ bias,
        float* __restrict__ out, int n_nodes) {
    int node = blockIdx.x * 8 + (threadIdx.x >> 5);
    if (node >= n_nodes) return;
    int lane = threadIdx.x & 31;
    int half = lane >> 4;
    int li = lane & 15;
    int beg = g_offs[node], end = g_offs[node + 1];

    float4 acc = make_float4(0.f, 0.f, 0.f, 0.f);
    int e = beg + half;
    for (; e + 6 < end; e += 8) {
        uint2 s0 = g_srcw[e];
        uint2 s1 = g_srcw[e + 2];
        uint2 s2 = g_srcw[e + 4];
        uint2 s3 = g_srcw[e + 6];
        float4 v0 = *(const float4*)&H[(long)s0.x * 64 + li * 4];
        float4 v1 = *(const float4*)&H[(long)s1.x * 64 + li * 4];
        float4 v2 = *(const float4*)&H[(long)s2.x * 64 + li * 4];
        float4 v3 = *(const float4*)&H[(long)s3.x * 64 + li * 4];
        float w0 = __uint_as_float(s0.y), w1 = __uint_as_float(s1.y);
        float w2 = __uint_as_float(s2.y), w3 = __uint_as_float(s3.y);
        acc.x = fmaf(v0.x, w0, acc.x); acc.y = fmaf(v0.y, w0, acc.y);
        acc.z = fmaf(v0.z, w0, acc.z); acc.w = fmaf(v0.w, w0, acc.w);
        acc.x = fmaf(v1.x, w1, acc.x); acc.y = fmaf(v1.y, w1, acc.y);
        acc.z = fmaf(v1.z, w1, acc.z); acc.w = fmaf(v1.w, w1, acc.w);
        acc.x = fmaf(v2.x, w2, acc.x); acc.y = fmaf(v2.y, w2, acc.y);
        acc.z = fmaf(v2.z, w2, acc.z); acc.w = fmaf(v2.w, w2, acc.w);
        acc.x = fmaf(v3.x, w3, acc.x); acc.y = fmaf(v3.y, w3, acc.y);
        acc.z = fmaf(v3.z, w3, acc.z); acc.w = fmaf(v3.w, w3, acc.w);
    }
    for (; e < end; e += 2) {
        uint2 s0 = g_srcw[e];
        float4 v0 = *(const float4*)&H[(long)s0.x * 64 + li * 4];
        float w0 = __uint_as_float(s0.y);
        acc.x = fmaf(v0.x, w0, acc.x); acc.y = fmaf(v0.y, w0, acc.y);
        acc.z = fmaf(v0.z, w0, acc.z); acc.w = fmaf(v0.w, w0, acc.w);
    }

    const unsigned fm = 0xFFFFFFFFu;
    acc.x += __shfl_down_sync(fm, acc.x, 16);
    acc.y += __shfl_down_sync(fm, acc.y, 16);
    acc.z += __shfl_down_sync(fm, acc.z, 16);
    acc.w += __shfl_down_sync(fm, acc.w, 16);

    if (half == 0) {
        if (bias) {
            float4 b = __ldg((const float4*)&bias[li * 4]);
            acc.x += b.x; acc.y += b.y; acc.z += b.z; acc.w += b.w;
        }
        *(float4*)&out[(long)node * 64 + li * 4] = acc;
    }
}

// ---------------------------------------------------------------------------
// Fused GEMM, double-buffered, tf32 tensor-core 1-pass (ah*bh), ~3e-4 rel.
//   MODE 0: f(a) = mask ? a*2 : 0
//   MODE 1: f(a) = mask ? relu(a + bias[k])*2 : 0
// BM=128, BN=64, BK=16, 256 threads = 8 warps.
// ---------------------------------------------------------------------------
template <int K, int MODE>
__global__ __launch_bounds__(256) void gemm_tc(
        const float* __restrict__ A,
        const void* __restrict__ mask,
        const float* __restrict__ W,
        const float* __restrict__ bias,
        float* __restrict__ C, int n_rows) {
    __shared__ float As[2][128][20];
    __shared__ float Bs[2][16][72];
    __shared__ float sb[64];

    const int tid = threadIdx.x;
    const int mkind = g_flags[1];
    if (MODE == 1) {
        if (tid < 64) sb[tid] = bias[tid];
        __syncthreads();
    }

    const int row0 = blockIdx.x * 128;
    const int warp = tid >> 5;
    const int lane = tid & 31;
    const int gid = lane >> 2;
    const int tig = lane & 3;
    const int m0 = warp * 16;

    int arow[2], aq[2];
    #pragma unroll
    for (int i = 0; i < 2; i++) {
        int lin = tid + i * 256;
        arow[i] = lin >> 2;
        aq[i]   = lin & 3;
    }
    const int bkk = tid >> 4;
    const int bn4 = tid & 15;

    float4 ra[2];
    uint4  rm[2];
    float4 rb;

    auto load_tile = [&](int k0) {
        #pragma unroll
        for (int i = 0; i < 2; i++) {
            int gr = row0 + arow[i];
            ra[i] = make_float4(0.f, 0.f, 0.f, 0.f);
            rm[i] = make_uint4(0u, 0u, 0u, 0u);
            if (gr < n_rows) {
                long gi = (long)gr * K + k0 + aq[i] * 4;
                ra[i] = *(const float4*)&A[gi];
                if (mkind == 0) {
                    rm[i].x = *(const unsigned int*)((const unsigned char*)mask + gi);
                } else if (mkind == 1) {
                    float4 f = *(const float4*)((const float*)mask + gi);
                    rm[i] = make_uint4(__float_as_uint(f.x), __float_as_uint(f.y),
                                       __float_as_uint(f.z), __float_as_uint(f.w));
                } else {
                    rm[i] = *(const uint4*)((const int*)mask + gi);
                }
            }
        }
        rb = *(const float4*)&W[(long)(k0 + bkk) * 64 + bn4 * 4];
    };

    auto store_tile = [&](int buf, int k0) {
        #pragma unroll
        for (int i = 0; i < 2; i++) {
            float4 v = ra[i];
            float mv[4];
            if (mkind == 0) {
                unsigned int mw = rm[i].x;
                mv[0] = (mw & 0x000000FFu) ? 2.f : 0.f;
                mv[1] = (mw & 0x0000FF00u) ? 2.f : 0.f;
                mv[2] = (mw & 0x00FF0000u) ? 2.f : 0.f;
                mv[3] = (mw & 0xFF000000u) ? 2.f : 0.f;
            } else {
                mv[0] = rm[i].x ? 2.f : 0.f;
                mv[1] = rm[i].y ? 2.f : 0.f;
                mv[2] = rm[i].z ? 2.f : 0.f;
                mv[3] = rm[i].w ? 2.f : 0.f;
            }
            if (MODE == 1) {
                int kb = k0 + aq[i] * 4;
                v.x = fmaxf(v.x + sb[kb + 0], 0.f);
                v.y = fmaxf(v.y + sb[kb + 1], 0.f);
                v.z = fmaxf(v.z + sb[kb + 2], 0.f);
                v.w = fmaxf(v.w + sb[kb + 3], 0.f);
            }
            float4 o = make_float4(v.x * mv[0], v.y * mv[1], v.z * mv[2], v.w * mv[3]);
            *(float4*)&As[buf][arow[i]][aq[i] * 4] = o;
        }
        *(float4*)&Bs[buf][bkk][bn4 * 4] = rb;
    };

    float acc[8][4] = {};
    const int NIT = K / 16;

    load_tile(0);
    store_tile(0, 0);
    __syncthreads();

    for (int it = 0; it < NIT; it++) {
        int cur = it & 1;
        if (it + 1 < NIT) load_tile((it + 1) * 16);

        #pragma unroll
        for (int ks = 0; ks < 2; ks++) {
            int kk = ks * 8;
            uint32_t ah[4];
            ah[0] = f2tf32(As[cur][m0 + gid    ][kk + tig]);
            ah[1] = f2tf32(As[cur][m0 + gid + 8][kk + tig]);
            ah[2] = f2tf32(As[cur][m0 + gid    ][kk + tig + 4]);
            ah[3] = f2tf32(As[cur][m0 + gid + 8][kk + tig + 4]);

            #pragma unroll
            for (int nt = 0; nt < 8; nt++) {
                int n0 = nt * 8;
                uint32_t bh[2];
                bh[0] = f2tf32(Bs[cur][kk + tig    ][n0 + gid]);
                bh[1] = f2tf32(Bs[cur][kk + tig + 4][n0 + gid]);
                mma_tf32(acc[nt], ah, bh);
            }
        }

        if (it + 1 < NIT) {
            store_tile(cur ^ 1, (it + 1) * 16);
            __syncthreads();
        }
    }

    int ra_ = row0 + m0 + gid;
    int rb_ = ra_ + 8;
    #pragma unroll
    for (int nt = 0; nt < 8; nt++) {
        int col = nt * 8 + 2 * tig;
        if (ra_ < n_rows)
            *(float2*)&C[(long)ra_ * 64 + col] = make_float2(acc[nt][0], acc[nt][1]);
        if (rb_ < n_rows)
            *(float2*)&C[(long)rb_ * 64 + col] = make_float2(acc[nt][2], acc[nt][3]);
    }
}

// ---------------------------------------------------------------------------
// inputs: x, edge_index(2xE), edge_weight, W1, b1, W2, b2, mask1, mask2
// CSR build runs on a side stream, overlapped with GEMM1 (independent work).
// ---------------------------------------------------------------------------
extern "C" void kernel_launch(void* const* d_in, const int* in_sizes, int n_in,
                              void* d_out, int out_size) {
    const float* x  = (const float*)d_in[0];
    const void* ei  = d_in[1];
    const float* ew = (const float*)d_in[2];
    const float* W1 = (const float*)d_in[3];
    const float* b1 = (const float*)d_in[4];
    const float* W2 = (const float*)d_in[5];
    const float* b2 = (const float*)d_in[6];
    const void* m1  = d_in[7];
    const void* m2  = d_in[8];
    float* out = (float*)d_out;

    int n_nodes = in_sizes[0] / 384;
    int n_edges = in_sizes[2];

    float *H1, *AGG1, *H2;
    cudaGetSymbolAddress((void**)&H1, g_H1);
    cudaGetSymbolAddress((void**)&AGG1, g_AGG1);
    cudaGetSymbolAddress((void**)&H2, g_H2);

    // One-time host-object setup (no device memory; identical work every call)
    static cudaStream_t s2 = nullptr;
    static cudaEvent_t evFork = nullptr, evJoin = nullptr;
    if (!s2) {
        cudaStreamCreateWithFlags(&s2, cudaStreamNonBlocking);
        cudaEventCreateWithFlags(&evFork, cudaEventDisableTiming);
        cudaEventCreateWithFlags(&evJoin, cudaEventDisableTiming);
    }

    detect_kernel<<<1, 32>>>((const int*)ei, (const unsigned int*)m1);

    // fork: CSR build on s2, GEMM1 on main stream — independent until agg1
    cudaEventRecord(evFork, 0);
    cudaStreamWaitEvent(s2, evFork, 0);

    int nb = (n_nodes + 1023) / 1024;
    zero_deg<<<(n_nodes + 255) / 256, 256, 0, s2>>>(n_nodes);
    hist_kernel<<<(n_edges + 255) / 256, 256, 0, s2>>>(ei, n_edges);
    scan1_kernel<<<nb, 1024, 0, s2>>>(n_nodes);
    scan2_kernel<<<1, 32, 0, s2>>>(nb, n_nodes, n_edges);
    scan3_kernel<<<(n_nodes + 255) / 256, 256, 0, s2>>>(n_nodes);
    fill_kernel<<<(n_edges + 255) / 256, 256, 0, s2>>>(ei, ew, n_edges);
    cudaEventRecord(evJoin, s2);

    int gb = (n_nodes + 127) / 128;
    int ab = (n_nodes + 7) / 8;
    gemm_tc<384, 0><<<gb, 256>>>(x, m1, W1, nullptr, H1, n_nodes);

    // join: agg1 needs both GEMM1 (H1) and CSR
    cudaStreamWaitEvent(0, evJoin, 0);
    agg_kernel<<<ab, 256>>>(H1, nullptr, AGG1, n_nodes);
    gemm_tc<64, 1><<<gb, 256>>>(AGG1, m2, W2, b1, H2, n_nodes);
    agg_kernel<<<ab, 256>>>(H2, b2, out, n_nodes);
}

// round 17
// speedup vs baseline: 1.9463x; 1.0843x over previous
#include <cuda_runtime.h>
#include <cuda_fp16.h>
#include <cstdint>

#define D 64
#define NMAX 100000
#define EMAX 1600000

__device__ __half g_H1[NMAX * D];
__device__ float  g_AGG1[NMAX * D];
__device__ __half g_H2[NMAX * D];
__device__ int    g_deg[NMAX];
__device__ int    g_offs[NMAX + 1];
__device__ int    g_cursor[NMAX];
__device__ uint2  g_srcw[EMAX];
__device__ int    g_bsum[128];

// flags[0]: edge_index is int64 (1) or int32 (0)
// flags[1]: mask elem kind: 0 = uint8, 1 = float32, 2 = int32
__device__ int g_flags[2];

// ---- tf32 helpers -----------------------------------------------------------
__device__ __forceinline__ uint32_t f2tf32(float f) {
    uint32_t r;
    asm("cvt.rna.tf32.f32 %0, %1;" : "=r"(r) : "f"(f));
    return r;
}
__device__ __forceinline__ void mma_tf32(float* c, const uint32_t* a, const uint32_t* b) {
    asm volatile(
        "mma.sync.aligned.m16n8k8.row.col.f32.tf32.tf32.f32 "
        "{%0,%1,%2,%3}, {%4,%5,%6,%7}, {%8,%9}, {%0,%1,%2,%3};"
        : "+f"(c[0]), "+f"(c[1]), "+f"(c[2]), "+f"(c[3])
        : "r"(a[0]), "r"(a[1]), "r"(a[2]), "r"(a[3]), "r"(b[0]), "r"(b[1]));
}

// ---------------------------------------------------------------------------
// Dtype detection — warp-parallel.
// ---------------------------------------------------------------------------
__global__ void detect_kernel(const int* __restrict__ ei_words,
                              const unsigned int* __restrict__ mask_words) {
    int lane = threadIdx.x;
    int odd_nonzero = 0;
    #pragma unroll
    for (int i = 0; i < 8; i++)
        if (ei_words[2 * (lane + i * 32) + 1] != 0) odd_nonzero = 1;
    int is64 = !__any_sync(0xFFFFFFFFu, odd_nonzero);

    int saw_f32 = 0, saw_hi = 0;
    #pragma unroll
    for (int i = 0; i < 128; i++) {
        unsigned int w = mask_words[lane + i * 32];
        if (w == 0x3F800000u) saw_f32 = 1;
        if ((w & 0xFFFFFF00u) != 0) saw_hi = 1;
    }
    int any_f32 = __any_sync(0xFFFFFFFFu, saw_f32);
    int any_hi  = __any_sync(0xFFFFFFFFu, saw_hi);
    if (lane == 0) {
        g_flags[0] = is64;
        g_flags[1] = any_f32 ? 1 : (any_hi ? 0 : 2);
    }
}

// ---------------------------------------------------------------------------
// CSR build: zero -> hist -> scan(3) -> fill
// ---------------------------------------------------------------------------
__global__ void zero_deg(int n) {
    int i = blockIdx.x * blockDim.x + threadIdx.x;
    if (i < n) g_deg[i] = 0;
}

__global__ void hist_kernel(const void* __restrict__ ei_raw, int n_edges) {
    int e = blockIdx.x * blockDim.x + threadIdx.x;
    if (e >= n_edges) return;
    int d = g_flags[0] ? (int)((const long long*)ei_raw)[n_edges + e]
                       : ((const int*)ei_raw)[n_edges + e];
    atomicAdd(&g_deg[d], 1);
}

__global__ void scan1_kernel(int n) {
    __shared__ int sh[1024];
    int i = blockIdx.x * 1024 + threadIdx.x;
    int v = (i < n) ? g_deg[i] : 0;
    sh[threadIdx.x] = v;
    __syncthreads();
    #pragma unroll
    for (int off = 1; off < 1024; off <<= 1) {
        int t = (threadIdx.x >= off) ? sh[threadIdx.x - off] : 0;
        __syncthreads();
        sh[threadIdx.x] += t;
        __syncthreads();
    }
    if (i < n) g_offs[i] = sh[threadIdx.x] - v;
    if (threadIdx.x == 1023) g_bsum[blockIdx.x] = sh[1023];
}

__global__ void scan2_kernel(int nb, int n, int n_edges) {
    if (threadIdx.x == 0) {
        int run = 0;
        for (int b = 0; b < nb; b++) { int t = g_bsum[b]; g_bsum[b] = run; run += t; }
        g_offs[n] = n_edges;
    }
}

__global__ void scan3_kernel(int n) {
    int i = blockIdx.x * blockDim.x + threadIdx.x;
    if (i >= n) return;
    int o = g_offs[i] + g_bsum[i >> 10];
    g_offs[i] = o;
    g_cursor[i] = o;
}

__global__ void fill_kernel(const void* __restrict__ ei_raw,
                            const float* __restrict__ ew, int n_edges) {
    int e = blockIdx.x * blockDim.x + threadIdx.x;
    if (e >= n_edges) return;
    int s, d;
    if (g_flags[0]) {
        const long long* ei = (const long long*)ei_raw;
        s = (int)ei[e];
        d = (int)ei[n_edges + e];
    } else {
        const int* ei = (const int*)ei_raw;
        s = ei[e];
        d = ei[n_edges + e];
    }
    int p = atomicAdd(&g_cursor[d], 1);
    g_srcw[p] = make_uint2((unsigned)s, __float_as_uint(__ldg(&ew[e])));
}

// ---------------------------------------------------------------------------
// CSR aggregation over fp16 H: out[node] = sum H[src]*w (+ bias), fp32 acc/out.
// One warp per node; two half-warps x two edges, 16 lanes x 4 cols (8B loads).
// ---------------------------------------------------------------------------
__global__ __launch_bounds__(256) void agg_kernel(
        const __half* __restrict__ H,
        const float* __restrict__ bias,
        float* __restrict__ out, int n_nodes) {
    int node = blockIdx.x * 8 + (threadIdx.x >> 5);
    if (node >= n_nodes) return;
    int lane = threadIdx.x & 31;
    int half = lane >> 4;
    int li = lane & 15;
    int beg = g_offs[node], end = g_offs[node + 1];

    float4 acc = make_float4(0.f, 0.f, 0.f, 0.f);
    int e = beg + half;
    for (; e + 6 < end; e += 8) {
        uint2 s0 = g_srcw[e];
        uint2 s1 = g_srcw[e + 2];
        uint2 s2 = g_srcw[e + 4];
        uint2 s3 = g_srcw[e + 6];
        const __half2* p0 = (const __half2*)&H[(long)s0.x * 64 + li * 4];
        const __half2* p1 = (const __half2*)&H[(long)s1.x * 64 + li * 4];
        const __half2* p2 = (const __half2*)&H[(long)s2.x * 64 + li * 4];
        const __half2* p3 = (const __half2*)&H[(long)s3.x * 64 + li * 4];
        float2 a0 = __half22float2(p0[0]), b0 = __half22float2(p0[1]);
        float2 a1 = __half22float2(p1[0]), b1 = __half22float2(p1[1]);
        float2 a2 = __half22float2(p2[0]), b2 = __half22float2(p2[1]);
        float2 a3 = __half22float2(p3[0]), b3 = __half22float2(p3[1]);
        float w0 = __uint_as_float(s0.y), w1 = __uint_as_float(s1.y);
        float w2 = __uint_as_float(s2.y), w3 = __uint_as_float(s3.y);
        acc.x = fmaf(a0.x, w0, acc.x); acc.y = fmaf(a0.y, w0, acc.y);
        acc.z = fmaf(b0.x, w0, acc.z); acc.w = fmaf(b0.y, w0, acc.w);
        acc.x = fmaf(a1.x, w1, acc.x); acc.y = fmaf(a1.y, w1, acc.y);
        acc.z = fmaf(b1.x, w1, acc.z); acc.w = fmaf(b1.y, w1, acc.w);
        acc.x = fmaf(a2.x, w2, acc.x); acc.y = fmaf(a2.y, w2, acc.y);
        acc.z = fmaf(b2.x, w2, acc.z); acc.w = fmaf(b2.y, w2, acc.w);
        acc.x = fmaf(a3.x, w3, acc.x); acc.y = fmaf(a3.y, w3, acc.y);
        acc.z = fmaf(b3.x, w3, acc.z); acc.w = fmaf(b3.y, w3, acc.w);
    }
    for (; e < end; e += 2) {
        uint2 s0 = g_srcw[e];
        const __half2* p0 = (const __half2*)&H[(long)s0.x * 64 + li * 4];
        float2 a0 = __half22float2(p0[0]), b0 = __half22float2(p0[1]);
        float w0 = __uint_as_float(s0.y);
        acc.x = fmaf(a0.x, w0, acc.x); acc.y = fmaf(a0.y, w0, acc.y);
        acc.z = fmaf(b0.x, w0, acc.z); acc.w = fmaf(b0.y, w0, acc.w);
    }

    const unsigned fm = 0xFFFFFFFFu;
    acc.x += __shfl_down_sync(fm, acc.x, 16);
    acc.y += __shfl_down_sync(fm, acc.y, 16);
    acc.z += __shfl_down_sync(fm, acc.z, 16);
    acc.w += __shfl_down_sync(fm, acc.w, 16);

    if (half == 0) {
        if (bias) {
            float4 b = __ldg((const float4*)&bias[li * 4]);
            acc.x += b.x; acc.y += b.y; acc.z += b.z; acc.w += b.w;
        }
        *(float4*)&out[(long)node * 64 + li * 4] = acc;
    }
}

// ---------------------------------------------------------------------------
// Fused GEMM, double-buffered, tf32 tensor-core 1-pass; fp16 output.
//   MODE 0: f(a) = mask ? a*2 : 0
//   MODE 1: f(a) = mask ? relu(a + bias[k])*2 : 0
// BM=128, BN=64, BK=16, 256 threads = 8 warps.
// ---------------------------------------------------------------------------
template <int K, int MODE>
__global__ __launch_bounds__(256) void gemm_tc(
        const float* __restrict__ A,
        const void* __restrict__ mask,
        const float* __restrict__ W,
        const float* __restrict__ bias,
        __half* __restrict__ C, int n_rows) {
    __shared__ float As[2][128][20];
    __shared__ float Bs[2][16][72];
    __shared__ float sb[64];

    const int tid = threadIdx.x;
    const int mkind = g_flags[1];
    if (MODE == 1) {
        if (tid < 64) sb[tid] = bias[tid];
        __syncthreads();
    }

    const int row0 = blockIdx.x * 128;
    const int warp = tid >> 5;
    const int lane = tid & 31;
    const int gid = lane >> 2;
    const int tig = lane & 3;
    const int m0 = warp * 16;

    int arow[2], aq[2];
    #pragma unroll
    for (int i = 0; i < 2; i++) {
        int lin = tid + i * 256;
        arow[i] = lin >> 2;
        aq[i]   = lin & 3;
    }
    const int bkk = tid >> 4;
    const int bn4 = tid & 15;

    float4 ra[2];
    uint4  rm[2];
    float4 rb;

    auto load_tile = [&](int k0) {
        #pragma unroll
        for (int i = 0; i < 2; i++) {
            int gr = row0 + arow[i];
            ra[i] = make_float4(0.f, 0.f, 0.f, 0.f);
            rm[i] = make_uint4(0u, 0u, 0u, 0u);
            if (gr < n_rows) {
                long gi = (long)gr * K + k0 + aq[i] * 4;
                ra[i] = *(const float4*)&A[gi];
                if (mkind == 0) {
                    rm[i].x = *(const unsigned int*)((const unsigned char*)mask + gi);
                } else if (mkind == 1) {
                    float4 f = *(const float4*)((const float*)mask + gi);
                    rm[i] = make_uint4(__float_as_uint(f.x), __float_as_uint(f.y),
                                       __float_as_uint(f.z), __float_as_uint(f.w));
                } else {
                    rm[i] = *(const uint4*)((const int*)mask + gi);
                }
            }
        }
        rb = *(const float4*)&W[(long)(k0 + bkk) * 64 + bn4 * 4];
    };

    auto store_tile = [&](int buf, int k0) {
        #pragma unroll
        for (int i = 0; i < 2; i++) {
            float4 v = ra[i];
            float mv[4];
            if (mkind == 0) {
                unsigned int mw = rm[i].x;
                mv[0] = (mw & 0x000000FFu) ? 2.f : 0.f;
                mv[1] = (mw & 0x0000FF00u) ? 2.f : 0.f;
                mv[2] = (mw & 0x00FF0000u) ? 2.f : 0.f;
                mv[3] = (mw & 0xFF000000u) ? 2.f : 0.f;
            } else {
                mv[0] = rm[i].x ? 2.f : 0.f;
                mv[1] = rm[i].y ? 2.f : 0.f;
                mv[2] = rm[i].z ? 2.f : 0.f;
                mv[3] = rm[i].w ? 2.f : 0.f;
            }
            if (MODE == 1) {
                int kb = k0 + aq[i] * 4;
                v.x = fmaxf(v.x + sb[kb + 0], 0.f);
                v.y = fmaxf(v.y + sb[kb + 1], 0.f);
                v.z = fmaxf(v.z + sb[kb + 2], 0.f);
                v.w = fmaxf(v.w + sb[kb + 3], 0.f);
            }
            float4 o = make_float4(v.x * mv[0], v.y * mv[1], v.z * mv[2], v.w * mv[3]);
            *(float4*)&As[buf][arow[i]][aq[i] * 4] = o;
        }
        *(float4*)&Bs[buf][bkk][bn4 * 4] = rb;
    };

    float acc[8][4] = {};
    const int NIT = K / 16;

    load_tile(0);
    store_tile(0, 0);
    __syncthreads();

    for (int it = 0; it < NIT; it++) {
        int cur = it & 1;
        if (it + 1 < NIT) load_tile((it + 1) * 16);

        #pragma unroll
        for (int ks = 0; ks < 2; ks++) {
            int kk = ks * 8;
            uint32_t ah[4];
            ah[0] = f2tf32(As[cur][m0 + gid    ][kk + tig]);
            ah[1] = f2tf32(As[cur][m0 + gid + 8][kk + tig]);
            ah[2] = f2tf32(As[cur][m0 + gid    ][kk + tig + 4]);
            ah[3] = f2tf32(As[cur][m0 + gid + 8][kk + tig + 4]);

            #pragma unroll
            for (int nt = 0; nt < 8; nt++) {
                int n0 = nt * 8;
                uint32_t bh[2];
                bh[0] = f2tf32(Bs[cur][kk + tig    ][n0 + gid]);
                bh[1] = f2tf32(Bs[cur][kk + tig + 4][n0 + gid]);
                mma_tf32(acc[nt], ah, bh);
            }
        }

        if (it + 1 < NIT) {
            store_tile(cur ^ 1, (it + 1) * 16);
            __syncthreads();
        }
    }

    int ra_ = row0 + m0 + gid;
    int rb_ = ra_ + 8;
    #pragma unroll
    for (int nt = 0; nt < 8; nt++) {
        int col = nt * 8 + 2 * tig;
        if (ra_ < n_rows)
            *(__half2*)&C[(long)ra_ * 64 + col] = __floats2half2_rn(acc[nt][0], acc[nt][1]);
        if (rb_ < n_rows)
            *(__half2*)&C[(long)rb_ * 64 + col] = __floats2half2_rn(acc[nt][2], acc[nt][3]);
    }
}

// ---------------------------------------------------------------------------
// Variant with fp32 A but fp32 AGG input for layer 2 (input is AGG1 float).
// Same kernel works: A is float* in both cases.
// ---------------------------------------------------------------------------

// inputs: x, edge_index(2xE), edge_weight, W1, b1, W2, b2, mask1, mask2
extern "C" void kernel_launch(void* const* d_in, const int* in_sizes, int n_in,
                              void* d_out, int out_size) {
    const float* x  = (const float*)d_in[0];
    const void* ei  = d_in[1];
    const float* ew = (const float*)d_in[2];
    const float* W1 = (const float*)d_in[3];
    const float* b1 = (const float*)d_in[4];
    const float* W2 = (const float*)d_in[5];
    const float* b2 = (const float*)d_in[6];
    const void* m1  = d_in[7];
    const void* m2  = d_in[8];
    float* out = (float*)d_out;

    int n_nodes = in_sizes[0] / 384;
    int n_edges = in_sizes[2];

    __half *H1, *H2;
    float *AGG1;
    cudaGetSymbolAddress((void**)&H1, g_H1);
    cudaGetSymbolAddress((void**)&AGG1, g_AGG1);
    cudaGetSymbolAddress((void**)&H2, g_H2);

    static cudaStream_t s2 = nullptr;
    static cudaEvent_t evFork = nullptr, evJoin = nullptr;
    if (!s2) {
        cudaStreamCreateWithFlags(&s2, cudaStreamNonBlocking);
        cudaEventCreateWithFlags(&evFork, cudaEventDisableTiming);
        cudaEventCreateWithFlags(&evJoin, cudaEventDisableTiming);
    }

    detect_kernel<<<1, 32>>>((const int*)ei, (const unsigned int*)m1);

    // fork: CSR build on s2 concurrent with GEMM1
    cudaEventRecord(evFork, 0);
    cudaStreamWaitEvent(s2, evFork, 0);

    int nb = (n_nodes + 1023) / 1024;
    zero_deg<<<(n_nodes + 255) / 256, 256, 0, s2>>>(n_nodes);
    hist_kernel<<<(n_edges + 255) / 256, 256, 0, s2>>>(ei, n_edges);
    scan1_kernel<<<nb, 1024, 0, s2>>>(n_nodes);
    scan2_kernel<<<1, 32, 0, s2>>>(nb, n_nodes, n_edges);
    scan3_kernel<<<(n_nodes + 255) / 256, 256, 0, s2>>>(n_nodes);
    fill_kernel<<<(n_edges + 255) / 256, 256, 0, s2>>>(ei, ew, n_edges);
    cudaEventRecord(evJoin, s2);

    int gb = (n_nodes + 127) / 128;
    int ab = (n_nodes + 7) / 8;
    gemm_tc<384, 0><<<gb, 256>>>(x, m1, W1, nullptr, H1, n_nodes);

    cudaStreamWaitEvent(0, evJoin, 0);
    agg_kernel<<<ab, 256>>>(H1, nullptr, AGG1, n_nodes);
    gemm_tc<64, 1><<<gb, 256>>>(AGG1, m2, W2, b1, H2, n_nodes);
    agg_kernel<<<ab, 256>>>(H2, b2, out, n_nodes);
}